// round 5
// baseline (speedup 1.0000x reference)
#include <cuda_runtime.h>

#define NN 10000
#define NE 320000
#define HD 64
#define NLAYERS 4
#define TE 128   // edges per tile (edge kernel)
#define TNN 64   // nodes per tile (node kernel)

typedef unsigned long long ull;

// ---------------- scratch state (allocation-free) ----------------
__device__ __align__(16) float g_h[NN * HD];
__device__ __align__(16) float g_agg[NN * HD];
__device__ float g_x[NN * 3];
__device__ float g_v[NN * 3];
__device__ float g_iv[NN * 3];
__device__ float g_acc3[NN * 3];
__device__ float g_cnt[NN];
__device__ int g_edge64;

__device__ __forceinline__ float silu_f(float x) {
    return __fdividef(x, 1.0f + __expf(-x));
}

// packed f32x2 helpers
__device__ __forceinline__ ull d2(float x) {
    ull r;
    unsigned u = __float_as_uint(x);
    asm("mov.b64 %0, {%1, %1};" : "=l"(r) : "r"(u));
    return r;
}
__device__ __forceinline__ ull ffma2(ull a, ull b, ull c) {
    ull d;
    asm("fma.rn.f32x2 %0, %1, %2, %3;" : "=l"(d) : "l"(a), "l"(b), "l"(c));
    return d;
}
__device__ __forceinline__ float2 u2f(ull v) {
    unsigned lo, hi;
    asm("mov.b64 {%0, %1}, %2;" : "=r"(lo), "=r"(hi) : "l"(v));
    return make_float2(__uint_as_float(lo), __uint_as_float(hi));
}

// swizzled staging index (16B-granule xor)
__device__ __forceinline__ int sidx(int k, int e, int RW) {
    return k * RW + ((((e >> 2) ^ ((k >> 2) & 7)) << 2) | (e & 3));
}

__device__ __forceinline__ int edge_idx(const void* edges, long long i) {
    if (g_edge64) return (int)((const long long*)edges)[i];
    return ((const int*)edges)[i];
}

__global__ void k_detect(const void* edges) {
    const int* p = (const int*)edges;
    int is64 = 1;
    for (int i = 1; i < 64; i += 2)
        if (p[i] != 0) is64 = 0;
    g_edge64 = is64;
}

__global__ void k_init(const float* __restrict__ his, const float* __restrict__ loc,
                       const float* __restrict__ vel, const float* __restrict__ emb_w,
                       const float* __restrict__ emb_b) {
    int idx = blockIdx.x * blockDim.x + threadIdx.x;
    if (idx < NN * HD) {
        int n = idx >> 6, j = idx & 63;
        float a = emb_b[j];
#pragma unroll
        for (int i = 0; i < 4; i++) a = fmaf(his[n * 4 + i], emb_w[i * 64 + j], a);
        g_h[idx] = a;
        g_agg[idx] = 0.f;
    }
    if (idx < NN * 3) {
        g_x[idx] = loc[idx];
        g_v[idx] = vel[idx];
        g_acc3[idx] = 0.f;
    }
    if (idx < NN) {
        float vx = vel[idx * 3], vy = vel[idx * 3 + 1], vz = vel[idx * 3 + 2];
        float inv = 1.0f / (sqrtf(vx * vx + vy * vy + vz * vz) + 1e-8f);
        g_iv[idx * 3] = vx * inv;
        g_iv[idx * 3 + 1] = vy * inv;
        g_iv[idx * 3 + 2] = vz * inv;
        g_cnt[idx] = 0.f;
    }
}

// ---- FFMA2 GEMM with PRE-DUPLICATED weights: zero MOVs in inner loop ----
// wd row layout: 128 floats per k-row, feature j duplicated at [2j, 2j+1].
// Per-thread tile: 8 edges (4 pairs) x 4 features. Per k: 4x LDS.128 + 16 FFMA2.
template <int RW>
__device__ __forceinline__ void gemm_d(const float* __restrict__ st,
                                       const float* __restrict__ wd,
                                       const float* __restrict__ bias,
                                       ull (&acc)[4][4], int fc, int er, int K) {
#pragma unroll
    for (int j = 0; j < 4; j++) {
        ull bb = d2(bias[4 * fc + j]);
#pragma unroll
        for (int p = 0; p < 4; p++) acc[p][j] = bb;
    }
    const int eg0 = 2 * er, eg1 = 2 * er + 1;
    const float* wp = wd + 8 * fc;
    const int Km = K & ~3;
#pragma unroll 2
    for (int k0 = 0; k0 < Km; k0 += 4) {
        int s = (k0 >> 2) & 7;
        int o0 = ((eg0 ^ s) << 2), o1 = ((eg1 ^ s) << 2);
#pragma unroll
        for (int kk = 0; kk < 4; kk++) {
            const float* rp = st + (k0 + kk) * RW;
            ulonglong2 aA = *(const ulonglong2*)(rp + o0);
            ulonglong2 aB = *(const ulonglong2*)(rp + o1);
            const float* wr = wp + (k0 + kk) * 128;
            ulonglong2 wA = *(const ulonglong2*)(wr);      // (w0,w0),(w1,w1)
            ulonglong2 wB = *(const ulonglong2*)(wr + 4);  // (w2,w2),(w3,w3)
            acc[0][0] = ffma2(aA.x, wA.x, acc[0][0]);
            acc[1][0] = ffma2(aA.y, wA.x, acc[1][0]);
            acc[2][0] = ffma2(aB.x, wA.x, acc[2][0]);
            acc[3][0] = ffma2(aB.y, wA.x, acc[3][0]);
            acc[0][1] = ffma2(aA.x, wA.y, acc[0][1]);
            acc[1][1] = ffma2(aA.y, wA.y, acc[1][1]);
            acc[2][1] = ffma2(aB.x, wA.y, acc[2][1]);
            acc[3][1] = ffma2(aB.y, wA.y, acc[3][1]);
            acc[0][2] = ffma2(aA.x, wB.x, acc[0][2]);
            acc[1][2] = ffma2(aA.y, wB.x, acc[1][2]);
            acc[2][2] = ffma2(aB.x, wB.x, acc[2][2]);
            acc[3][2] = ffma2(aB.y, wB.x, acc[3][2]);
            acc[0][3] = ffma2(aA.x, wB.y, acc[0][3]);
            acc[1][3] = ffma2(aA.y, wB.y, acc[1][3]);
            acc[2][3] = ffma2(aB.x, wB.y, acc[2][3]);
            acc[3][3] = ffma2(aB.y, wB.y, acc[3][3]);
        }
    }
    for (int k = Km; k < K; k++) {
        int s = (k >> 2) & 7;
        const float* rp = st + k * RW;
        ulonglong2 aA = *(const ulonglong2*)(rp + ((eg0 ^ s) << 2));
        ulonglong2 aB = *(const ulonglong2*)(rp + ((eg1 ^ s) << 2));
        const float* wr = wp + k * 128;
        ulonglong2 wA = *(const ulonglong2*)(wr);
        ulonglong2 wB = *(const ulonglong2*)(wr + 4);
        acc[0][0] = ffma2(aA.x, wA.x, acc[0][0]);
        acc[1][0] = ffma2(aA.y, wA.x, acc[1][0]);
        acc[2][0] = ffma2(aB.x, wA.x, acc[2][0]);
        acc[3][0] = ffma2(aB.y, wA.x, acc[3][0]);
        acc[0][1] = ffma2(aA.x, wA.y, acc[0][1]);
        acc[1][1] = ffma2(aA.y, wA.y, acc[1][1]);
        acc[2][1] = ffma2(aB.x, wA.y, acc[2][1]);
        acc[3][1] = ffma2(aB.y, wA.y, acc[3][1]);
        acc[0][2] = ffma2(aA.x, wB.x, acc[0][2]);
        acc[1][2] = ffma2(aA.y, wB.x, acc[1][2]);
        acc[2][2] = ffma2(aB.x, wB.x, acc[2][2]);
        acc[3][2] = ffma2(aB.y, wB.x, acc[3][2]);
        acc[0][3] = ffma2(aA.x, wB.y, acc[0][3]);
        acc[1][3] = ffma2(aA.y, wB.y, acc[1][3]);
        acc[2][3] = ffma2(aB.x, wB.y, acc[2][3]);
        acc[3][3] = ffma2(aB.y, wB.y, acc[3][3]);
    }
}

// silu + transposed (feature-major, swizzled) store of the 8x4 tile
template <int RW>
__device__ __forceinline__ void store_silu_t(float* st, ull (&acc)[4][4], int fc, int er) {
    int s = fc & 7;
    int o0 = (((2 * er) ^ s) << 2), o1 = (((2 * er + 1) ^ s) << 2);
#pragma unroll
    for (int j = 0; j < 4; j++) {
        int r = 4 * fc + j;
        float2 f0 = u2f(acc[0][j]), f1 = u2f(acc[1][j]);
        float2 f2 = u2f(acc[2][j]), f3 = u2f(acc[3][j]);
        float4 v0 = make_float4(silu_f(f0.x), silu_f(f0.y), silu_f(f1.x), silu_f(f1.y));
        float4 v1 = make_float4(silu_f(f2.x), silu_f(f2.y), silu_f(f3.x), silu_f(f3.y));
        *(float4*)(st + r * RW + o0) = v0;
        *(float4*)(st + r * RW + o1) = v1;
    }
}

// dup-fill: wd[k*128 + 2j, 2j+1] = w[k*64 + j]
__device__ __forceinline__ void dup_fill(float* wd, const float* __restrict__ w,
                                         int nk, int tid, int nthr) {
    for (int i = tid; i < nk * 32; i += nthr) {
        int k = i >> 5, j2 = i & 31;
        float2 v = ((const float2*)w)[k * 32 + j2];
        *(float4*)(wd + k * 128 + 4 * j2) = make_float4(v.x, v.x, v.y, v.y);
    }
}

// ---------------- edge kernel: 128-edge tiles, 256 threads ----------------
__global__ void __launch_bounds__(256, 1)
    k_edge(const void* __restrict__ edges, const float* __restrict__ edge_attr,
           const float* __restrict__ ew1, const float* __restrict__ eb1,
           const float* __restrict__ ew2, const float* __restrict__ eb2,
           const float* __restrict__ cw1, const float* __restrict__ cb1,
           const float* __restrict__ cw2) {
    extern __shared__ float sm[];
    float* w1d = sm;                    // 131*128 = 16768 (duplicated)
    float* w2d = w1d + 16768;           // 8192
    float* w3d = w2d + 8192;            // 8192
    float* ins = w3d + 8192;            // 131*128 = 16768 (swizzled staging)
    float* b1s = ins + 16768;           // 64
    float* b2s = b1s + 64;
    float* b3s = b2s + 64;
    float* c2s = b3s + 64;
    float* gts = c2s + 64;              // 128
    float* cds = gts + 128;             // 3*128
    int* rs = (int*)(cds + 384);        // 128
    int* cs = rs + 128;                 // 128

    const int tid = threadIdx.x;
    const int fc = tid & 15;   // feature quad
    const int er = tid >> 4;   // edge octet

    dup_fill(w1d, ew1, 131, tid, 256);
    dup_fill(w2d, ew2, 64, tid, 256);
    dup_fill(w3d, cw1, 64, tid, 256);
    if (tid < 64) {
        b1s[tid] = eb1[tid];
        b2s[tid] = eb2[tid];
        b3s[tid] = cb1[tid];
        c2s[tid] = cw2[tid];
    }

    const int e = tid & 127;
    const int half = tid >> 7;
    const int ntile = NE / TE;
    for (int t = blockIdx.x; t < ntile; t += gridDim.x) {
        __syncthreads();
        long long e0 = (long long)t * TE;
        if (tid < TE) {
            rs[tid] = edge_idx(edges, e0 + tid);
            cs[tid] = edge_idx(edges, (long long)NE + e0 + tid);
        }
        __syncthreads();
        if (tid < TE) {
            int r = rs[e], c = cs[e];
            float dx = g_x[r * 3] - g_x[c * 3];
            float dy = g_x[r * 3 + 1] - g_x[c * 3 + 1];
            float dz = g_x[r * 3 + 2] - g_x[c * 3 + 2];
            cds[e] = dx;
            cds[128 + e] = dy;
            cds[256 + e] = dz;
            ins[sidx(128, e, 128)] = dx * dx + dy * dy + dz * dz;
            float2 ea = *(const float2*)&edge_attr[(e0 + e) * 2];
            ins[sidx(129, e, 128)] = ea.x;
            ins[sidx(130, e, 128)] = ea.y;
        }
        {
            int r = rs[e], c = cs[e];
#pragma unroll
            for (int q = 0; q < 8; q++) {
                int kq = half * 8 + q;
                float4 hv = *(const float4*)&g_h[r * 64 + 4 * kq];
                ins[sidx(4 * kq + 0, e, 128)] = hv.x;
                ins[sidx(4 * kq + 1, e, 128)] = hv.y;
                ins[sidx(4 * kq + 2, e, 128)] = hv.z;
                ins[sidx(4 * kq + 3, e, 128)] = hv.w;
                float4 hc = *(const float4*)&g_h[c * 64 + 4 * kq];
                ins[sidx(64 + 4 * kq + 0, e, 128)] = hc.x;
                ins[sidx(64 + 4 * kq + 1, e, 128)] = hc.y;
                ins[sidx(64 + 4 * kq + 2, e, 128)] = hc.z;
                ins[sidx(64 + 4 * kq + 3, e, 128)] = hc.w;
            }
        }
        __syncthreads();

        ull acc[4][4];
        // GEMM1: [128e,131]@[131,64] + b1, silu
        gemm_d<128>(ins, w1d, b1s, acc, fc, er, 131);
        __syncthreads();
        store_silu_t<128>(ins, acc, fc, er);
        __syncthreads();

        // GEMM2: @[64,64] + b2, silu -> ef
        gemm_d<128>(ins, w2d, b2s, acc, fc, er, 64);
        __syncthreads();
        store_silu_t<128>(ins, acc, fc, er);
        __syncthreads();

        // GEMM3: ef@cw1 + b3, silu, dot cw2 -> gate
        gemm_d<128>(ins, w3d, b3s, acc, fc, er, 64);
        {
            float g[8] = {0.f, 0.f, 0.f, 0.f, 0.f, 0.f, 0.f, 0.f};
#pragma unroll
            for (int p = 0; p < 4; p++)
#pragma unroll
                for (int j = 0; j < 4; j++) {
                    float2 f = u2f(acc[p][j]);
                    float c = c2s[4 * fc + j];
                    g[2 * p] = fmaf(silu_f(f.x), c, g[2 * p]);
                    g[2 * p + 1] = fmaf(silu_f(f.y), c, g[2 * p + 1]);
                }
#pragma unroll
            for (int m = 1; m < 16; m <<= 1)
#pragma unroll
                for (int i = 0; i < 8; i++)
                    g[i] += __shfl_xor_sync(0xffffffffu, g[i], m);
            if (fc == 0)
#pragma unroll
                for (int i = 0; i < 8; i++) gts[8 * er + i] = g[i];
        }
        __syncthreads();

        // scatter: agg += ef, acc3 += cd*gate, cnt += 1
        {
            int r = rs[e];
#pragma unroll
            for (int q = 0; q < 32; q++) {
                int f = half * 32 + q;
                atomicAdd(&g_agg[r * 64 + f], ins[sidx(f, e, 128)]);
            }
            if (half == 0) {
                float gg = gts[e];
                atomicAdd(&g_acc3[r * 3 + 0], cds[e] * gg);
                atomicAdd(&g_acc3[r * 3 + 1], cds[128 + e] * gg);
                atomicAdd(&g_acc3[r * 3 + 2], cds[256 + e] * gg);
                atomicAdd(&g_cnt[r], 1.0f);
            }
        }
    }
}

// ======== node kernel (R2 version, unchanged) ========
template <int RW>
__device__ __forceinline__ void gemm_t(const float* __restrict__ st,
                                       const float* __restrict__ w,
                                       const float* __restrict__ bias,
                                       ull (&acc)[4][4], int fc, int er, int K) {
#pragma unroll
    for (int j = 0; j < 4; j++) {
        ull bb = d2(bias[4 * fc + j]);
#pragma unroll
        for (int p = 0; p < 4; p++) acc[p][j] = bb;
    }
    const int eg0 = 2 * er, eg1 = 2 * er + 1;
#pragma unroll 2
    for (int k0 = 0; k0 < K; k0 += 4) {
        int ss = (k0 >> 2) & 7;
        int o0 = ((eg0 ^ ss) << 2), o1 = ((eg1 ^ ss) << 2);
#pragma unroll
        for (int kk = 0; kk < 4; kk++) {
            const float* rp = st + (k0 + kk) * RW;
            ulonglong2 aA = *(const ulonglong2*)(rp + o0);
            ulonglong2 aB = *(const ulonglong2*)(rp + o1);
            float4 wv = *(const float4*)(w + (k0 + kk) * 64 + 4 * fc);
            ull b0 = d2(wv.x), b1 = d2(wv.y), b2 = d2(wv.z), b3 = d2(wv.w);
            acc[0][0] = ffma2(aA.x, b0, acc[0][0]);
            acc[1][0] = ffma2(aA.y, b0, acc[1][0]);
            acc[2][0] = ffma2(aB.x, b0, acc[2][0]);
            acc[3][0] = ffma2(aB.y, b0, acc[3][0]);
            acc[0][1] = ffma2(aA.x, b1, acc[0][1]);
            acc[1][1] = ffma2(aA.y, b1, acc[1][1]);
            acc[2][1] = ffma2(aB.x, b1, acc[2][1]);
            acc[3][1] = ffma2(aB.y, b1, acc[3][1]);
            acc[0][2] = ffma2(aA.x, b2, acc[0][2]);
            acc[1][2] = ffma2(aA.y, b2, acc[1][2]);
            acc[2][2] = ffma2(aB.x, b2, acc[2][2]);
            acc[3][2] = ffma2(aB.y, b2, acc[3][2]);
            acc[0][3] = ffma2(aA.x, b3, acc[0][3]);
            acc[1][3] = ffma2(aA.y, b3, acc[1][3]);
            acc[2][3] = ffma2(aB.x, b3, acc[2][3]);
            acc[3][3] = ffma2(aB.y, b3, acc[3][3]);
        }
    }
}

__global__ void __launch_bounds__(128, 2)
    k_node(const float* __restrict__ nw1, const float* __restrict__ nb1,
           const float* __restrict__ nw2, const float* __restrict__ nb2,
           const float* __restrict__ vw1, const float* __restrict__ vb1,
           const float* __restrict__ vw2, const float* __restrict__ vb2) {
    extern __shared__ float sm[];
    float* wn1 = sm;
    float* wn2 = wn1 + 8192;
    float* wv1 = wn2 + 4096;
    float* us = wv1 + 4096;
    float* nb1s = us + 8192;
    float* nb2s = nb1s + 64;
    float* vb1s = nb2s + 64;
    float* vw2s = vb1s + 64;
    float* phis = vw2s + 64;

    const int tid = threadIdx.x;
    const int fc = tid & 15;
    const int er = tid >> 4;

    for (int i = tid; i < 2048; i += 128) ((float4*)wn1)[i] = ((const float4*)nw1)[i];
    for (int i = tid; i < 1024; i += 128) {
        ((float4*)wn2)[i] = ((const float4*)nw2)[i];
        ((float4*)wv1)[i] = ((const float4*)vw1)[i];
    }
    if (tid < 64) {
        nb1s[tid] = nb1[tid];
        nb2s[tid] = nb2[tid];
        vb1s[tid] = vb1[tid];
        vw2s[tid] = vw2[tid];
    }
    const float vb2v = vb2[0];

    const int e = tid & 63;
    const int half = tid >> 6;
    const int ntile = (NN + TNN - 1) / TNN;
    for (int t = blockIdx.x; t < ntile; t += gridDim.x) {
        __syncthreads();
        int n0 = t * TNN;
        int n = n0 + e;
#pragma unroll
        for (int q = 0; q < 8; q++) {
            int kq = half * 8 + q;
            float4 hv = make_float4(0, 0, 0, 0), av = make_float4(0, 0, 0, 0);
            if (n < NN) {
                hv = *(const float4*)&g_h[n * 64 + 4 * kq];
                av = *(const float4*)&g_agg[n * 64 + 4 * kq];
            }
            us[sidx(4 * kq + 0, e, 64)] = hv.x;
            us[sidx(4 * kq + 1, e, 64)] = hv.y;
            us[sidx(4 * kq + 2, e, 64)] = hv.z;
            us[sidx(4 * kq + 3, e, 64)] = hv.w;
            us[sidx(64 + 4 * kq + 0, e, 64)] = av.x;
            us[sidx(64 + 4 * kq + 1, e, 64)] = av.y;
            us[sidx(64 + 4 * kq + 2, e, 64)] = av.z;
            us[sidx(64 + 4 * kq + 3, e, 64)] = av.w;
        }
        __syncthreads();

        ull acc[4][4];
        gemm_t<64>(us, wv1, vb1s, acc, fc, er, 64);
        {
            float g[8] = {0.f, 0.f, 0.f, 0.f, 0.f, 0.f, 0.f, 0.f};
#pragma unroll
            for (int p = 0; p < 4; p++)
#pragma unroll
                for (int j = 0; j < 4; j++) {
                    float2 f = u2f(acc[p][j]);
                    float c = vw2s[4 * fc + j];
                    g[2 * p] = fmaf(silu_f(f.x), c, g[2 * p]);
                    g[2 * p + 1] = fmaf(silu_f(f.y), c, g[2 * p + 1]);
                }
#pragma unroll
            for (int m = 1; m < 16; m <<= 1)
#pragma unroll
                for (int i = 0; i < 8; i++)
                    g[i] += __shfl_xor_sync(0xffffffffu, g[i], m);
            if (fc == 0)
#pragma unroll
                for (int i = 0; i < 8; i++) phis[8 * er + i] = g[i] + vb2v;
        }

        gemm_t<64>(us, wn1, nb1s, acc, fc, er, 128);
        __syncthreads();
        store_silu_t<64>(us + 64 * 64, acc, fc, er);
        __syncthreads();

        gemm_t<64>(us + 64 * 64, wn2, nb2s, acc, fc, er, 64);
#pragma unroll
        for (int p = 0; p < 4; p++) {
            int nlo = n0 + 8 * er + 2 * p, nhi = nlo + 1;
#pragma unroll
            for (int j = 0; j < 4; j++) {
                float2 f = u2f(acc[p][j]);
                if (nlo < NN) g_h[nlo * 64 + 4 * fc + j] += f.x;
                if (nhi < NN) g_h[nhi * 64 + 4 * fc + j] += f.y;
            }
        }

        if (tid < TNN) {
            int nu = n0 + tid;
            if (nu < NN) {
                float cnt = g_cnt[nu];
                float inv = 1.0f / fmaxf(cnt, 1.0f);
                float phi = phis[tid];
#pragma unroll
                for (int d = 0; d < 3; d++) {
                    float a = g_acc3[nu * 3 + d] * inv;
                    float vn = g_v[nu * 3 + d] + a + phi * g_iv[nu * 3 + d];
                    g_v[nu * 3 + d] = vn;
                    g_x[nu * 3 + d] += vn;
                    g_acc3[nu * 3 + d] = 0.f;
                }
                g_cnt[nu] = 0.f;
            }
        }
        for (int i = tid; i < TNN * 64; i += 128) {
            int nz = n0 + (i >> 6);
            if (nz < NN) g_agg[nz * 64 + (i & 63)] = 0.f;
        }
    }
}

// ---------------- output: [x | h | v] ----------------
__global__ void k_copyout(float* __restrict__ out) {
    int i = blockIdx.x * blockDim.x + threadIdx.x;
    if (i < NN * 3) out[i] = g_x[i];
    if (i < NN * HD) out[NN * 3 + i] = g_h[i];
    if (i < NN * 3) out[NN * 3 + NN * HD + i] = g_v[i];
}

extern "C" void kernel_launch(void* const* d_in, const int* in_sizes, int n_in,
                              void* d_out, int out_size) {
    const float* his = (const float*)d_in[0];
    const float* loc = (const float*)d_in[1];
    const void* edges = d_in[2];
    const float* vel = (const float*)d_in[3];
    const float* eattr = (const float*)d_in[4];
    const float* emb_w = (const float*)d_in[5];
    const float* emb_b = (const float*)d_in[6];
    const float* ew1 = (const float*)d_in[7];
    const float* eb1 = (const float*)d_in[8];
    const float* ew2 = (const float*)d_in[9];
    const float* eb2 = (const float*)d_in[10];
    const float* nw1 = (const float*)d_in[11];
    const float* nb1 = (const float*)d_in[12];
    const float* nw2 = (const float*)d_in[13];
    const float* nb2 = (const float*)d_in[14];
    const float* cw1 = (const float*)d_in[15];
    const float* cb1 = (const float*)d_in[16];
    const float* cw2 = (const float*)d_in[17];
    const float* vw1 = (const float*)d_in[18];
    const float* vb1 = (const float*)d_in[19];
    const float* vw2 = (const float*)d_in[20];
    const float* vb2 = (const float*)d_in[21];

    // edge smem: w1d 16768 + w2d 8192 + w3d 8192 + ins 16768 + biases 256
    //            + gts 128 + cds 384 = 50688 floats + 256 ints
    size_t esm = (size_t)50688 * 4 + 256 * sizeof(int);
    size_t nsm = (size_t)(8192 + 4096 + 4096 + 8192 + 4 * 64 + 64) * 4;
    cudaFuncSetAttribute(k_edge, cudaFuncAttributeMaxDynamicSharedMemorySize, (int)esm);
    cudaFuncSetAttribute(k_node, cudaFuncAttributeMaxDynamicSharedMemorySize, (int)nsm);

    k_detect<<<1, 1>>>(edges);
    k_init<<<(NN * HD + 255) / 256, 256>>>(his, loc, vel, emb_w, emb_b);
    for (int l = 0; l < NLAYERS; l++) {
        k_edge<<<148, 256, esm>>>(edges, eattr, ew1, eb1, ew2, eb2, cw1, cb1, cw2);
        k_node<<<157, 128, nsm>>>(nw1, nb1, nw2, nb2, vw1, vb1, vw2, vb2);
    }
    k_copyout<<<(NN * HD + 255) / 256, 256>>>((float*)d_out);
}

// round 6
// speedup vs baseline: 1.3152x; 1.3152x over previous
#include <cuda_runtime.h>

#define NN 10000
#define NE 320000
#define HD 64
#define NLAYERS 4
#define TE 256   // edges per tile (edge kernel)
#define TNN 64   // nodes per tile (node kernel)

typedef unsigned long long ull;

// ---------------- scratch state (allocation-free) ----------------
__device__ __align__(16) float g_h[NN * HD];
__device__ __align__(16) float g_agg[NN * HD];
__device__ float g_x[NN * 3];
__device__ float g_v[NN * 3];
__device__ float g_iv[NN * 3];
__device__ float g_acc3[NN * 3];
__device__ float g_cnt[NN];
__device__ int g_edge64;

__device__ __forceinline__ float silu_f(float x) {
    return __fdividef(x, 1.0f + __expf(-x));
}

// packed f32x2 helpers
__device__ __forceinline__ ull d2(float x) {
    ull r;
    unsigned u = __float_as_uint(x);
    asm("mov.b64 %0, {%1, %1};" : "=l"(r) : "r"(u));
    return r;
}
__device__ __forceinline__ ull ffma2(ull a, ull b, ull c) {
    ull d;
    asm("fma.rn.f32x2 %0, %1, %2, %3;" : "=l"(d) : "l"(a), "l"(b), "l"(c));
    return d;
}
__device__ __forceinline__ float2 u2f(ull v) {
    unsigned lo, hi;
    asm("mov.b64 {%0, %1}, %2;" : "=r"(lo), "=r"(hi) : "l"(v));
    return make_float2(__uint_as_float(lo), __uint_as_float(hi));
}

// swizzled staging index (16B-granule xor): conflict-free for both
// column-stores (gather/epilogue) and row-loads (GEMM A operands)
__device__ __forceinline__ int sidx(int k, int e, int RW) {
    return k * RW + ((((e >> 2) ^ ((k >> 2) & 7)) << 2) | (e & 3));
}

__device__ __forceinline__ int edge_idx(const void* edges, long long i) {
    if (g_edge64) return (int)((const long long*)edges)[i];
    return ((const int*)edges)[i];
}

__global__ void k_detect(const void* edges) {
    const int* p = (const int*)edges;
    int is64 = 1;
    for (int i = 1; i < 64; i += 2)
        if (p[i] != 0) is64 = 0;
    g_edge64 = is64;
}

__global__ void k_init(const float* __restrict__ his, const float* __restrict__ loc,
                       const float* __restrict__ vel, const float* __restrict__ emb_w,
                       const float* __restrict__ emb_b) {
    int idx = blockIdx.x * blockDim.x + threadIdx.x;
    if (idx < NN * HD) {
        int n = idx >> 6, j = idx & 63;
        float a = emb_b[j];
#pragma unroll
        for (int i = 0; i < 4; i++) a = fmaf(his[n * 4 + i], emb_w[i * 64 + j], a);
        g_h[idx] = a;
        g_agg[idx] = 0.f;
    }
    if (idx < NN * 3) {
        g_x[idx] = loc[idx];
        g_v[idx] = vel[idx];
        g_acc3[idx] = 0.f;
    }
    if (idx < NN) {
        float vx = vel[idx * 3], vy = vel[idx * 3 + 1], vz = vel[idx * 3 + 2];
        float inv = 1.0f / (sqrtf(vx * vx + vy * vy + vz * vz) + 1e-8f);
        g_iv[idx * 3] = vx * inv;
        g_iv[idx * 3 + 1] = vy * inv;
        g_iv[idx * 3 + 2] = vz * inv;
        g_cnt[idx] = 0.f;
    }
}

// ---- 8 edges x 8 features FFMA2 GEMM ----
// lane mapping: g = feature octet (lane>>2), E = edge octet (warp*4 + (lane&3)).
// A: 2x LDS.128/k, 4 distinct addrs/warp (8x broadcast) -> 1 wavefront each.
// W: 2x LDS.128/k at k*64+8g, 8 distinct x 16B = 128B contiguous -> 1 wavefront each.
__device__ __forceinline__ void gemm8(const float* __restrict__ st,
                                      const float* __restrict__ w,
                                      const float* __restrict__ bias,
                                      ull (&acc)[8][4], int g, int E, int K) {
#pragma unroll
    for (int j = 0; j < 8; j++) {
        ull bb = d2(bias[8 * g + j]);
#pragma unroll
        for (int p = 0; p < 4; p++) acc[j][p] = bb;
    }
    const int G0 = 2 * E, G1 = 2 * E + 1;
    const float* wp = w + 8 * g;
    const int Km = K & ~3;
#pragma unroll 2
    for (int k0 = 0; k0 < Km; k0 += 4) {
        int s = (k0 >> 2) & 7;
        int o0 = ((G0 ^ s) << 2), o1 = ((G1 ^ s) << 2);
#pragma unroll
        for (int kk = 0; kk < 4; kk++) {
            const float* rp = st + (k0 + kk) * 256;
            ulonglong2 aA = *(const ulonglong2*)(rp + o0);
            ulonglong2 aB = *(const ulonglong2*)(rp + o1);
            const float* wr = wp + (k0 + kk) * 64;
            float4 w0 = *(const float4*)(wr);
            float4 w1 = *(const float4*)(wr + 4);
            ull b0 = d2(w0.x), b1 = d2(w0.y), b2 = d2(w0.z), b3 = d2(w0.w);
            ull b4 = d2(w1.x), b5 = d2(w1.y), b6 = d2(w1.z), b7 = d2(w1.w);
            acc[0][0] = ffma2(aA.x, b0, acc[0][0]);
            acc[0][1] = ffma2(aA.y, b0, acc[0][1]);
            acc[0][2] = ffma2(aB.x, b0, acc[0][2]);
            acc[0][3] = ffma2(aB.y, b0, acc[0][3]);
            acc[1][0] = ffma2(aA.x, b1, acc[1][0]);
            acc[1][1] = ffma2(aA.y, b1, acc[1][1]);
            acc[1][2] = ffma2(aB.x, b1, acc[1][2]);
            acc[1][3] = ffma2(aB.y, b1, acc[1][3]);
            acc[2][0] = ffma2(aA.x, b2, acc[2][0]);
            acc[2][1] = ffma2(aA.y, b2, acc[2][1]);
            acc[2][2] = ffma2(aB.x, b2, acc[2][2]);
            acc[2][3] = ffma2(aB.y, b2, acc[2][3]);
            acc[3][0] = ffma2(aA.x, b3, acc[3][0]);
            acc[3][1] = ffma2(aA.y, b3, acc[3][1]);
            acc[3][2] = ffma2(aB.x, b3, acc[3][2]);
            acc[3][3] = ffma2(aB.y, b3, acc[3][3]);
            acc[4][0] = ffma2(aA.x, b4, acc[4][0]);
            acc[4][1] = ffma2(aA.y, b4, acc[4][1]);
            acc[4][2] = ffma2(aB.x, b4, acc[4][2]);
            acc[4][3] = ffma2(aB.y, b4, acc[4][3]);
            acc[5][0] = ffma2(aA.x, b5, acc[5][0]);
            acc[5][1] = ffma2(aA.y, b5, acc[5][1]);
            acc[5][2] = ffma2(aB.x, b5, acc[5][2]);
            acc[5][3] = ffma2(aB.y, b5, acc[5][3]);
            acc[6][0] = ffma2(aA.x, b6, acc[6][0]);
            acc[6][1] = ffma2(aA.y, b6, acc[6][1]);
            acc[6][2] = ffma2(aB.x, b6, acc[6][2]);
            acc[6][3] = ffma2(aB.y, b6, acc[6][3]);
            acc[7][0] = ffma2(aA.x, b7, acc[7][0]);
            acc[7][1] = ffma2(aA.y, b7, acc[7][1]);
            acc[7][2] = ffma2(aB.x, b7, acc[7][2]);
            acc[7][3] = ffma2(aB.y, b7, acc[7][3]);
        }
    }
    for (int k = Km; k < K; k++) {
        int s = (k >> 2) & 7;
        const float* rp = st + k * 256;
        ulonglong2 aA = *(const ulonglong2*)(rp + ((G0 ^ s) << 2));
        ulonglong2 aB = *(const ulonglong2*)(rp + ((G1 ^ s) << 2));
        const float* wr = wp + k * 64;
        float4 w0 = *(const float4*)(wr);
        float4 w1 = *(const float4*)(wr + 4);
        ull bb[8] = {d2(w0.x), d2(w0.y), d2(w0.z), d2(w0.w),
                     d2(w1.x), d2(w1.y), d2(w1.z), d2(w1.w)};
#pragma unroll
        for (int j = 0; j < 8; j++) {
            acc[j][0] = ffma2(aA.x, bb[j], acc[j][0]);
            acc[j][1] = ffma2(aA.y, bb[j], acc[j][1]);
            acc[j][2] = ffma2(aB.x, bb[j], acc[j][2]);
            acc[j][3] = ffma2(aB.y, bb[j], acc[j][3]);
        }
    }
}

// silu + feature-major swizzled store of the 8x8 tile
__device__ __forceinline__ void store8(float* st, ull (&acc)[8][4], int g, int E) {
#pragma unroll
    for (int j = 0; j < 8; j++) {
        int r = 8 * g + j;
        int s = (r >> 2) & 7;
        float2 f0 = u2f(acc[j][0]), f1 = u2f(acc[j][1]);
        float2 f2 = u2f(acc[j][2]), f3 = u2f(acc[j][3]);
        float4 v0 = make_float4(silu_f(f0.x), silu_f(f0.y), silu_f(f1.x), silu_f(f1.y));
        float4 v1 = make_float4(silu_f(f2.x), silu_f(f2.y), silu_f(f3.x), silu_f(f3.y));
        *(float4*)(st + r * 256 + (((2 * E) ^ s) << 2)) = v0;
        *(float4*)(st + r * 256 + (((2 * E + 1) ^ s) << 2)) = v1;
    }
}

// ---------------- edge kernel: 256-edge tiles, 256 threads ----------------
__global__ void __launch_bounds__(256, 1)
    k_edge(const void* __restrict__ edges, const float* __restrict__ edge_attr,
           const float* __restrict__ ew1, const float* __restrict__ eb1,
           const float* __restrict__ ew2, const float* __restrict__ eb2,
           const float* __restrict__ cw1, const float* __restrict__ cb1,
           const float* __restrict__ cw2) {
    extern __shared__ __align__(16) float sm[];
    float* w1s = sm;                    // 8384
    float* w2s = w1s + 8384;            // 4096
    float* w3s = w2s + 4096;            // 4096
    float* ins = w3s + 4096;            // 131*256 = 33536
    float* b1s = ins + 33536;           // 64
    float* b2s = b1s + 64;
    float* b3s = b2s + 64;
    float* c2s = b3s + 64;
    float* gts = c2s + 64;              // 256
    float* cds = gts + 256;             // 3*256
    int* rs = (int*)(cds + 768);        // 256
    int* cs = rs + 256;                 // 256

    const int tid = threadIdx.x;
    const int lane = tid & 31;
    const int warp = tid >> 5;
    const int g = lane >> 2;              // feature octet 0..7
    const int E = warp * 4 + (lane & 3);  // edge octet 0..31

    for (int i = tid; i < 2096; i += 256) ((float4*)w1s)[i] = ((const float4*)ew1)[i];
    for (int i = tid; i < 1024; i += 256) {
        ((float4*)w2s)[i] = ((const float4*)ew2)[i];
        ((float4*)w3s)[i] = ((const float4*)cw1)[i];
    }
    if (tid < 64) {
        b1s[tid] = eb1[tid];
        b2s[tid] = eb2[tid];
        b3s[tid] = cb1[tid];
        c2s[tid] = cw2[tid];
    }

    const int e = tid;   // one thread per edge for gather/scatter
    const int ntile = NE / TE;
    for (int t = blockIdx.x; t < ntile; t += gridDim.x) {
        __syncthreads();
        long long e0 = (long long)t * TE;
        rs[e] = edge_idx(edges, e0 + e);
        cs[e] = edge_idx(edges, (long long)NE + e0 + e);
        __syncthreads();
        {
            int r = rs[e], c = cs[e];
            float dx = g_x[r * 3] - g_x[c * 3];
            float dy = g_x[r * 3 + 1] - g_x[c * 3 + 1];
            float dz = g_x[r * 3 + 2] - g_x[c * 3 + 2];
            cds[e] = dx;
            cds[256 + e] = dy;
            cds[512 + e] = dz;
            ins[sidx(128, e, 256)] = dx * dx + dy * dy + dz * dz;
            float2 ea = *(const float2*)&edge_attr[(e0 + e) * 2];
            ins[sidx(129, e, 256)] = ea.x;
            ins[sidx(130, e, 256)] = ea.y;
            const float4* hp = (const float4*)&g_h[r * 64];
            const float4* hc = (const float4*)&g_h[c * 64];
#pragma unroll
            for (int q = 0; q < 16; q++) {
                float4 hv = hp[q];
                ins[sidx(4 * q + 0, e, 256)] = hv.x;
                ins[sidx(4 * q + 1, e, 256)] = hv.y;
                ins[sidx(4 * q + 2, e, 256)] = hv.z;
                ins[sidx(4 * q + 3, e, 256)] = hv.w;
                float4 hw = hc[q];
                ins[sidx(64 + 4 * q + 0, e, 256)] = hw.x;
                ins[sidx(64 + 4 * q + 1, e, 256)] = hw.y;
                ins[sidx(64 + 4 * q + 2, e, 256)] = hw.z;
                ins[sidx(64 + 4 * q + 3, e, 256)] = hw.w;
            }
        }
        __syncthreads();

        ull acc[8][4];
        // GEMM1: [256e,131]@[131,64] + b1, silu
        gemm8(ins, w1s, b1s, acc, g, E, 131);
        __syncthreads();
        store8(ins, acc, g, E);
        __syncthreads();

        // GEMM2: @[64,64] + b2, silu -> ef
        gemm8(ins, w2s, b2s, acc, g, E, 64);
        __syncthreads();
        store8(ins, acc, g, E);
        __syncthreads();

        // GEMM3: ef@cw1 + b3, silu, dot cw2 -> gate
        gemm8(ins, w3s, b3s, acc, g, E, 64);
        {
            float gv[8] = {0.f, 0.f, 0.f, 0.f, 0.f, 0.f, 0.f, 0.f};
#pragma unroll
            for (int j = 0; j < 8; j++) {
                float c = c2s[8 * g + j];
#pragma unroll
                for (int p = 0; p < 4; p++) {
                    float2 f = u2f(acc[j][p]);
                    gv[2 * p] = fmaf(silu_f(f.x), c, gv[2 * p]);
                    gv[2 * p + 1] = fmaf(silu_f(f.y), c, gv[2 * p + 1]);
                }
            }
            // reduce across feature octets (lane bits 2..4)
#pragma unroll
            for (int m = 4; m < 32; m <<= 1)
#pragma unroll
                for (int i = 0; i < 8; i++)
                    gv[i] += __shfl_xor_sync(0xffffffffu, gv[i], m);
            if (g == 0)
#pragma unroll
                for (int i = 0; i < 8; i++) gts[8 * E + i] = gv[i];
        }
        __syncthreads();

        // scatter: agg += ef, acc3 += cd*gate, cnt += 1  (1 thread per edge)
        {
            int r = rs[e];
#pragma unroll
            for (int f = 0; f < 64; f++)
                atomicAdd(&g_agg[r * 64 + f], ins[sidx(f, e, 256)]);
            float gg = gts[e];
            atomicAdd(&g_acc3[r * 3 + 0], cds[e] * gg);
            atomicAdd(&g_acc3[r * 3 + 1], cds[256 + e] * gg);
            atomicAdd(&g_acc3[r * 3 + 2], cds[512 + e] * gg);
            atomicAdd(&g_cnt[r], 1.0f);
        }
    }
}

// ======== node kernel (R2 version, proven) ========
template <int RW>
__device__ __forceinline__ void gemm_t(const float* __restrict__ st,
                                       const float* __restrict__ w,
                                       const float* __restrict__ bias,
                                       ull (&acc)[4][4], int fc, int er, int K) {
#pragma unroll
    for (int j = 0; j < 4; j++) {
        ull bb = d2(bias[4 * fc + j]);
#pragma unroll
        for (int p = 0; p < 4; p++) acc[p][j] = bb;
    }
    const int eg0 = 2 * er, eg1 = 2 * er + 1;
#pragma unroll 2
    for (int k0 = 0; k0 < K; k0 += 4) {
        int ss = (k0 >> 2) & 7;
        int o0 = ((eg0 ^ ss) << 2), o1 = ((eg1 ^ ss) << 2);
#pragma unroll
        for (int kk = 0; kk < 4; kk++) {
            const float* rp = st + (k0 + kk) * RW;
            ulonglong2 aA = *(const ulonglong2*)(rp + o0);
            ulonglong2 aB = *(const ulonglong2*)(rp + o1);
            float4 wv = *(const float4*)(w + (k0 + kk) * 64 + 4 * fc);
            ull b0 = d2(wv.x), b1 = d2(wv.y), b2 = d2(wv.z), b3 = d2(wv.w);
            acc[0][0] = ffma2(aA.x, b0, acc[0][0]);
            acc[1][0] = ffma2(aA.y, b0, acc[1][0]);
            acc[2][0] = ffma2(aB.x, b0, acc[2][0]);
            acc[3][0] = ffma2(aB.y, b0, acc[3][0]);
            acc[0][1] = ffma2(aA.x, b1, acc[0][1]);
            acc[1][1] = ffma2(aA.y, b1, acc[1][1]);
            acc[2][1] = ffma2(aB.x, b1, acc[2][1]);
            acc[3][1] = ffma2(aB.y, b1, acc[3][1]);
            acc[0][2] = ffma2(aA.x, b2, acc[0][2]);
            acc[1][2] = ffma2(aA.y, b2, acc[1][2]);
            acc[2][2] = ffma2(aB.x, b2, acc[2][2]);
            acc[3][2] = ffma2(aB.y, b2, acc[3][2]);
            acc[0][3] = ffma2(aA.x, b3, acc[0][3]);
            acc[1][3] = ffma2(aA.y, b3, acc[1][3]);
            acc[2][3] = ffma2(aB.x, b3, acc[2][3]);
            acc[3][3] = ffma2(aB.y, b3, acc[3][3]);
        }
    }
}

template <int RW>
__device__ __forceinline__ void store_silu_t4(float* st, ull (&acc)[4][4], int fc, int er) {
    int ss = fc & 7;
    int o0 = (((2 * er) ^ ss) << 2), o1 = (((2 * er + 1) ^ ss) << 2);
#pragma unroll
    for (int j = 0; j < 4; j++) {
        int r = 4 * fc + j;
        float2 f0 = u2f(acc[0][j]), f1 = u2f(acc[1][j]);
        float2 f2 = u2f(acc[2][j]), f3 = u2f(acc[3][j]);
        float4 v0 = make_float4(silu_f(f0.x), silu_f(f0.y), silu_f(f1.x), silu_f(f1.y));
        float4 v1 = make_float4(silu_f(f2.x), silu_f(f2.y), silu_f(f3.x), silu_f(f3.y));
        *(float4*)(st + r * RW + o0) = v0;
        *(float4*)(st + r * RW + o1) = v1;
    }
}

__global__ void __launch_bounds__(128, 2)
    k_node(const float* __restrict__ nw1, const float* __restrict__ nb1,
           const float* __restrict__ nw2, const float* __restrict__ nb2,
           const float* __restrict__ vw1, const float* __restrict__ vb1,
           const float* __restrict__ vw2, const float* __restrict__ vb2) {
    extern __shared__ __align__(16) float sm[];
    float* wn1 = sm;
    float* wn2 = wn1 + 8192;
    float* wv1 = wn2 + 4096;
    float* us = wv1 + 4096;
    float* nb1s = us + 8192;
    float* nb2s = nb1s + 64;
    float* vb1s = nb2s + 64;
    float* vw2s = vb1s + 64;
    float* phis = vw2s + 64;

    const int tid = threadIdx.x;
    const int fc = tid & 15;
    const int er = tid >> 4;

    for (int i = tid; i < 2048; i += 128) ((float4*)wn1)[i] = ((const float4*)nw1)[i];
    for (int i = tid; i < 1024; i += 128) {
        ((float4*)wn2)[i] = ((const float4*)nw2)[i];
        ((float4*)wv1)[i] = ((const float4*)vw1)[i];
    }
    if (tid < 64) {
        nb1s[tid] = nb1[tid];
        nb2s[tid] = nb2[tid];
        vb1s[tid] = vb1[tid];
        vw2s[tid] = vw2[tid];
    }
    const float vb2v = vb2[0];

    const int e = tid & 63;
    const int half = tid >> 6;
    const int ntile = (NN + TNN - 1) / TNN;
    for (int t = blockIdx.x; t < ntile; t += gridDim.x) {
        __syncthreads();
        int n0 = t * TNN;
        int n = n0 + e;
#pragma unroll
        for (int q = 0; q < 8; q++) {
            int kq = half * 8 + q;
            float4 hv = make_float4(0, 0, 0, 0), av = make_float4(0, 0, 0, 0);
            if (n < NN) {
                hv = *(const float4*)&g_h[n * 64 + 4 * kq];
                av = *(const float4*)&g_agg[n * 64 + 4 * kq];
            }
            us[sidx(4 * kq + 0, e, 64)] = hv.x;
            us[sidx(4 * kq + 1, e, 64)] = hv.y;
            us[sidx(4 * kq + 2, e, 64)] = hv.z;
            us[sidx(4 * kq + 3, e, 64)] = hv.w;
            us[sidx(64 + 4 * kq + 0, e, 64)] = av.x;
            us[sidx(64 + 4 * kq + 1, e, 64)] = av.y;
            us[sidx(64 + 4 * kq + 2, e, 64)] = av.z;
            us[sidx(64 + 4 * kq + 3, e, 64)] = av.w;
        }
        __syncthreads();

        ull acc[4][4];
        gemm_t<64>(us, wv1, vb1s, acc, fc, er, 64);
        {
            float gv[8] = {0.f, 0.f, 0.f, 0.f, 0.f, 0.f, 0.f, 0.f};
#pragma unroll
            for (int p = 0; p < 4; p++)
#pragma unroll
                for (int j = 0; j < 4; j++) {
                    float2 f = u2f(acc[p][j]);
                    float c = vw2s[4 * fc + j];
                    gv[2 * p] = fmaf(silu_f(f.x), c, gv[2 * p]);
                    gv[2 * p + 1] = fmaf(silu_f(f.y), c, gv[2 * p + 1]);
                }
#pragma unroll
            for (int m = 1; m < 16; m <<= 1)
#pragma unroll
                for (int i = 0; i < 8; i++)
                    gv[i] += __shfl_xor_sync(0xffffffffu, gv[i], m);
            if (fc == 0)
#pragma unroll
                for (int i = 0; i < 8; i++) phis[8 * er + i] = gv[i] + vb2v;
        }

        gemm_t<64>(us, wn1, nb1s, acc, fc, er, 128);
        __syncthreads();
        store_silu_t4<64>(us + 64 * 64, acc, fc, er);
        __syncthreads();

        gemm_t<64>(us + 64 * 64, wn2, nb2s, acc, fc, er, 64);
#pragma unroll
        for (int p = 0; p < 4; p++) {
            int nlo = n0 + 8 * er + 2 * p, nhi = nlo + 1;
#pragma unroll
            for (int j = 0; j < 4; j++) {
                float2 f = u2f(acc[p][j]);
                if (nlo < NN) g_h[nlo * 64 + 4 * fc + j] += f.x;
                if (nhi < NN) g_h[nhi * 64 + 4 * fc + j] += f.y;
            }
        }

        if (tid < TNN) {
            int nu = n0 + tid;
            if (nu < NN) {
                float cnt = g_cnt[nu];
                float inv = 1.0f / fmaxf(cnt, 1.0f);
                float phi = phis[tid];
#pragma unroll
                for (int d = 0; d < 3; d++) {
                    float a = g_acc3[nu * 3 + d] * inv;
                    float vn = g_v[nu * 3 + d] + a + phi * g_iv[nu * 3 + d];
                    g_v[nu * 3 + d] = vn;
                    g_x[nu * 3 + d] += vn;
                    g_acc3[nu * 3 + d] = 0.f;
                }
                g_cnt[nu] = 0.f;
            }
        }
        for (int i = tid; i < TNN * 64; i += 128) {
            int nz = n0 + (i >> 6);
            if (nz < NN) g_agg[nz * 64 + (i & 63)] = 0.f;
        }
    }
}

// ---------------- output: [x | h | v] ----------------
__global__ void k_copyout(float* __restrict__ out) {
    int i = blockIdx.x * blockDim.x + threadIdx.x;
    if (i < NN * 3) out[i] = g_x[i];
    if (i < NN * HD) out[NN * 3 + i] = g_h[i];
    if (i < NN * 3) out[NN * 3 + NN * HD + i] = g_v[i];
}

extern "C" void kernel_launch(void* const* d_in, const int* in_sizes, int n_in,
                              void* d_out, int out_size) {
    const float* his = (const float*)d_in[0];
    const float* loc = (const float*)d_in[1];
    const void* edges = d_in[2];
    const float* vel = (const float*)d_in[3];
    const float* eattr = (const float*)d_in[4];
    const float* emb_w = (const float*)d_in[5];
    const float* emb_b = (const float*)d_in[6];
    const float* ew1 = (const float*)d_in[7];
    const float* eb1 = (const float*)d_in[8];
    const float* ew2 = (const float*)d_in[9];
    const float* eb2 = (const float*)d_in[10];
    const float* nw1 = (const float*)d_in[11];
    const float* nb1 = (const float*)d_in[12];
    const float* nw2 = (const float*)d_in[13];
    const float* nb2 = (const float*)d_in[14];
    const float* cw1 = (const float*)d_in[15];
    const float* cb1 = (const float*)d_in[16];
    const float* cw2 = (const float*)d_in[17];
    const float* vw1 = (const float*)d_in[18];
    const float* vb1 = (const float*)d_in[19];
    const float* vw2 = (const float*)d_in[20];
    const float* vb2 = (const float*)d_in[21];

    // edge smem: w 16576 + ins 33536 + biases 256 + gts 256 + cds 768 = 51392 fl + 512 ints
    size_t esm = (size_t)51392 * 4 + 512 * sizeof(int);
    size_t nsm = (size_t)(8192 + 4096 + 4096 + 8192 + 4 * 64 + 64) * 4;
    cudaFuncSetAttribute(k_edge, cudaFuncAttributeMaxDynamicSharedMemorySize, (int)esm);
    cudaFuncSetAttribute(k_node, cudaFuncAttributeMaxDynamicSharedMemorySize, (int)nsm);

    k_detect<<<1, 1>>>(edges);
    k_init<<<(NN * HD + 255) / 256, 256>>>(his, loc, vel, emb_w, emb_b);
    for (int l = 0; l < NLAYERS; l++) {
        k_edge<<<148, 256, esm>>>(edges, eattr, ew1, eb1, ew2, eb2, cw1, cb1, cw2);
        k_node<<<157, 128, nsm>>>(nw1, nb1, nw2, nb2, vw1, vb1, vw2, vb2);
    }
    k_copyout<<<(NN * HD + 255) / 256, 256>>>((float*)d_out);
}

// round 7
// speedup vs baseline: 1.6428x; 1.2491x over previous
#include <cuda_runtime.h>

#define NN 10000
#define NE 320000
#define HD 64
#define NLAYERS 4
#define TE 256   // edges per tile (edge kernel)
#define TNN 64   // nodes per tile (node kernel)

typedef unsigned long long ull;

// ---------------- scratch state (allocation-free) ----------------
__device__ __align__(16) float g_h[NN * HD];
__device__ __align__(16) float g_agg[NN * HD];
__device__ __align__(16) float g_acc4[NN * 4];   // [dx,dy,dz,cnt] per node
__device__ float g_x[NN * 3];
__device__ float g_v[NN * 3];
__device__ float g_iv[NN * 3];
__device__ int g_edge64;

__device__ __forceinline__ float silu_f(float x) {
    return __fdividef(x, 1.0f + __expf(-x));
}

// packed f32x2 helpers
__device__ __forceinline__ ull d2(float x) {
    ull r;
    unsigned u = __float_as_uint(x);
    asm("mov.b64 %0, {%1, %1};" : "=l"(r) : "r"(u));
    return r;
}
__device__ __forceinline__ ull ffma2(ull a, ull b, ull c) {
    ull d;
    asm("fma.rn.f32x2 %0, %1, %2, %3;" : "=l"(d) : "l"(a), "l"(b), "l"(c));
    return d;
}
__device__ __forceinline__ float2 u2f(ull v) {
    unsigned lo, hi;
    asm("mov.b64 {%0, %1}, %2;" : "=r"(lo), "=r"(hi) : "l"(v));
    return make_float2(__uint_as_float(lo), __uint_as_float(hi));
}

// 16B vector reduction (sm_90+): 4 atomic f32 adds in one instruction
__device__ __forceinline__ void red4(float* p, float a, float b, float c, float d) {
    asm volatile("red.global.add.v4.f32 [%0], {%1, %2, %3, %4};"
                 :: "l"(p), "f"(a), "f"(b), "f"(c), "f"(d) : "memory");
}

// swizzled staging index (16B-granule xor): conflict-free for both
// column-stores (gather/epilogue) and row-loads (GEMM A operands)
__device__ __forceinline__ int sidx(int k, int e, int RW) {
    return k * RW + ((((e >> 2) ^ ((k >> 2) & 7)) << 2) | (e & 3));
}

__device__ __forceinline__ int edge_idx(const void* edges, long long i) {
    if (g_edge64) return (int)((const long long*)edges)[i];
    return ((const int*)edges)[i];
}

__global__ void k_detect(const void* edges) {
    const int* p = (const int*)edges;
    int is64 = 1;
    for (int i = 1; i < 64; i += 2)
        if (p[i] != 0) is64 = 0;
    g_edge64 = is64;
}

__global__ void k_init(const float* __restrict__ his, const float* __restrict__ loc,
                       const float* __restrict__ vel, const float* __restrict__ emb_w,
                       const float* __restrict__ emb_b) {
    int idx = blockIdx.x * blockDim.x + threadIdx.x;
    if (idx < NN * HD) {
        int n = idx >> 6, j = idx & 63;
        float a = emb_b[j];
#pragma unroll
        for (int i = 0; i < 4; i++) a = fmaf(his[n * 4 + i], emb_w[i * 64 + j], a);
        g_h[idx] = a;
        g_agg[idx] = 0.f;
    }
    if (idx < NN * 4) g_acc4[idx] = 0.f;
    if (idx < NN * 3) {
        g_x[idx] = loc[idx];
        g_v[idx] = vel[idx];
    }
    if (idx < NN) {
        float vx = vel[idx * 3], vy = vel[idx * 3 + 1], vz = vel[idx * 3 + 2];
        float inv = 1.0f / (sqrtf(vx * vx + vy * vy + vz * vz) + 1e-8f);
        g_iv[idx * 3] = vx * inv;
        g_iv[idx * 3 + 1] = vy * inv;
        g_iv[idx * 3 + 2] = vz * inv;
    }
}

// ---- edge GEMM: warp owns feature octet (uniform W), lane owns 4 edges ----
// Per k: 1 swizzled LDS.128 (A, conflict-free) + 2 uniform LDS.128 (W, broadcast)
// + 8 dup MOVs + 16 FFMA2. acc[8][2] = 32 regs only.
__device__ __forceinline__ void gemm_w(const float* __restrict__ st,
                                       const float* __restrict__ w,
                                       const float* __restrict__ bias,
                                       ull (&acc)[8][2], int wf, int lp, int K) {
#pragma unroll
    for (int j = 0; j < 8; j++) {
        ull bb = d2(bias[8 * wf + j]);
        acc[j][0] = bb;
        acc[j][1] = bb;
    }
    const float* wp = w + 8 * wf;
    const int Km = K & ~3;
    for (int k0 = 0; k0 < Km; k0 += 4) {
        int s = (k0 >> 2) & 7;
        int o = ((lp ^ s) << 2);
#pragma unroll
        for (int kk = 0; kk < 4; kk++) {
            ulonglong2 a = *(const ulonglong2*)(st + (k0 + kk) * 256 + o);
            const float* wr = wp + (k0 + kk) * 64;
            float4 w0 = *(const float4*)(wr);      // warp-uniform -> broadcast
            float4 w1 = *(const float4*)(wr + 4);  // warp-uniform -> broadcast
            ull b0 = d2(w0.x), b1 = d2(w0.y), b2 = d2(w0.z), b3 = d2(w0.w);
            ull b4 = d2(w1.x), b5 = d2(w1.y), b6 = d2(w1.z), b7 = d2(w1.w);
            acc[0][0] = ffma2(a.x, b0, acc[0][0]);
            acc[0][1] = ffma2(a.y, b0, acc[0][1]);
            acc[1][0] = ffma2(a.x, b1, acc[1][0]);
            acc[1][1] = ffma2(a.y, b1, acc[1][1]);
            acc[2][0] = ffma2(a.x, b2, acc[2][0]);
            acc[2][1] = ffma2(a.y, b2, acc[2][1]);
            acc[3][0] = ffma2(a.x, b3, acc[3][0]);
            acc[3][1] = ffma2(a.y, b3, acc[3][1]);
            acc[4][0] = ffma2(a.x, b4, acc[4][0]);
            acc[4][1] = ffma2(a.y, b4, acc[4][1]);
            acc[5][0] = ffma2(a.x, b5, acc[5][0]);
            acc[5][1] = ffma2(a.y, b5, acc[5][1]);
            acc[6][0] = ffma2(a.x, b6, acc[6][0]);
            acc[6][1] = ffma2(a.y, b6, acc[6][1]);
            acc[7][0] = ffma2(a.x, b7, acc[7][0]);
            acc[7][1] = ffma2(a.y, b7, acc[7][1]);
        }
    }
    for (int k = Km; k < K; k++) {
        int s = (k >> 2) & 7;
        ulonglong2 a = *(const ulonglong2*)(st + k * 256 + ((lp ^ s) << 2));
        const float* wr = wp + k * 64;
        float4 w0 = *(const float4*)(wr);
        float4 w1 = *(const float4*)(wr + 4);
        ull bb[8] = {d2(w0.x), d2(w0.y), d2(w0.z), d2(w0.w),
                     d2(w1.x), d2(w1.y), d2(w1.z), d2(w1.w)};
#pragma unroll
        for (int j = 0; j < 8; j++) {
            acc[j][0] = ffma2(a.x, bb[j], acc[j][0]);
            acc[j][1] = ffma2(a.y, bb[j], acc[j][1]);
        }
    }
}

// silu + feature-major swizzled store of the warp's 8x4 tile
__device__ __forceinline__ void store_w(float* st, ull (&acc)[8][2], int wf, int lp) {
#pragma unroll
    for (int j = 0; j < 8; j++) {
        int r = 8 * wf + j;
        int s = (r >> 2) & 7;
        float2 f0 = u2f(acc[j][0]), f1 = u2f(acc[j][1]);
        *(float4*)(st + r * 256 + ((lp ^ s) << 2)) =
            make_float4(silu_f(f0.x), silu_f(f0.y), silu_f(f1.x), silu_f(f1.y));
    }
}

// ---------------- edge kernel: 256-edge tiles, 512 threads ----------------
__global__ void __launch_bounds__(512, 1)
    k_edge(const void* __restrict__ edges, const float* __restrict__ edge_attr,
           const float* __restrict__ ew1, const float* __restrict__ eb1,
           const float* __restrict__ ew2, const float* __restrict__ eb2,
           const float* __restrict__ cw1, const float* __restrict__ cb1,
           const float* __restrict__ cw2) {
    extern __shared__ __align__(16) float sm[];
    float* w1s = sm;                    // 8384
    float* w2s = w1s + 8384;            // 4096
    float* w3s = w2s + 4096;            // 4096
    float* ins = w3s + 4096;            // 131*256 = 33536
    float* part = ins + 33536;          // 8*256 gate partials
    float* b1s = part + 2048;           // 64
    float* b2s = b1s + 64;
    float* b3s = b2s + 64;
    float* c2s = b3s + 64;
    float* cds = c2s + 64;              // 3*256
    int* rs = (int*)(cds + 768);        // 256
    int* cs = rs + 256;                 // 256

    const int tid = threadIdx.x;
    const int lane = tid & 31;
    const int warp = tid >> 5;
    const int wf = warp & 7;              // feature octet
    const int we = warp >> 3;             // edge half (0/1)
    const int lp = we * 32 + lane;        // edge granule 0..63 (edges 4lp..4lp+3)
    const int e = tid & 255;
    const int which = tid >> 8;           // 0: h[row] rows 0..63, 1: h[col] rows 64..127

    for (int i = tid; i < 2096; i += 512) ((float4*)w1s)[i] = ((const float4*)ew1)[i];
    for (int i = tid; i < 1024; i += 512) {
        ((float4*)w2s)[i] = ((const float4*)ew2)[i];
        ((float4*)w3s)[i] = ((const float4*)cw1)[i];
    }
    if (tid < 64) {
        b1s[tid] = eb1[tid];
        b2s[tid] = eb2[tid];
        b3s[tid] = cb1[tid];
        c2s[tid] = cw2[tid];
    }

    const int ntile = NE / TE;
    for (int t = blockIdx.x; t < ntile; t += gridDim.x) {
        __syncthreads();
        long long e0 = (long long)t * TE;
        if (which == 0) {
            rs[e] = edge_idx(edges, e0 + e);
            cs[e] = edge_idx(edges, (long long)NE + e0 + e);
        }
        __syncthreads();
        // gather h into transposed swizzled staging (2 threads per edge)
        {
            int node = which ? cs[e] : rs[e];
            const float4* hp = (const float4*)&g_h[node * 64];
#pragma unroll
            for (int q = 0; q < 16; q++) {
                float4 hv = hp[q];
                int r0 = which * 64 + 4 * q;
                ins[sidx(r0 + 0, e, 256)] = hv.x;
                ins[sidx(r0 + 1, e, 256)] = hv.y;
                ins[sidx(r0 + 2, e, 256)] = hv.z;
                ins[sidx(r0 + 3, e, 256)] = hv.w;
            }
        }
        if (which == 0) {
            int r = rs[e], c = cs[e];
            float dx = g_x[r * 3] - g_x[c * 3];
            float dy = g_x[r * 3 + 1] - g_x[c * 3 + 1];
            float dz = g_x[r * 3 + 2] - g_x[c * 3 + 2];
            cds[e] = dx;
            cds[256 + e] = dy;
            cds[512 + e] = dz;
            ins[sidx(128, e, 256)] = dx * dx + dy * dy + dz * dz;
            float2 ea = *(const float2*)&edge_attr[(e0 + e) * 2];
            ins[sidx(129, e, 256)] = ea.x;
            ins[sidx(130, e, 256)] = ea.y;
        }
        __syncthreads();

        ull acc[8][2];
        // GEMM1: [256e,131]@[131,64] + b1, silu
        gemm_w(ins, w1s, b1s, acc, wf, lp, 131);
        __syncthreads();
        store_w(ins, acc, wf, lp);
        __syncthreads();

        // GEMM2: @[64,64] + b2, silu -> ef
        gemm_w(ins, w2s, b2s, acc, wf, lp, 64);
        __syncthreads();
        store_w(ins, acc, wf, lp);
        __syncthreads();

        // GEMM3: ef@cw1 + b3, silu, dot cw2 -> per-warp gate partials
        gemm_w(ins, w3s, b3s, acc, wf, lp, 64);
        {
            float g0 = 0.f, g1 = 0.f, g2 = 0.f, g3 = 0.f;
#pragma unroll
            for (int j = 0; j < 8; j++) {
                float c = c2s[8 * wf + j];
                float2 f0 = u2f(acc[j][0]), f1 = u2f(acc[j][1]);
                g0 = fmaf(silu_f(f0.x), c, g0);
                g1 = fmaf(silu_f(f0.y), c, g1);
                g2 = fmaf(silu_f(f1.x), c, g2);
                g3 = fmaf(silu_f(f1.y), c, g3);
            }
            *(float4*)(part + wf * 256 + 4 * lp) = make_float4(g0, g1, g2, g3);
        }
        __syncthreads();

        // scatter: agg += ef (vector red), acc4 += [cd*gate, 1]
        {
            int r = rs[e];
#pragma unroll
            for (int q = 0; q < 8; q++) {
                int f0 = which * 32 + 4 * q;
                float v0 = ins[sidx(f0 + 0, e, 256)];
                float v1 = ins[sidx(f0 + 1, e, 256)];
                float v2 = ins[sidx(f0 + 2, e, 256)];
                float v3 = ins[sidx(f0 + 3, e, 256)];
                red4(&g_agg[r * 64 + f0], v0, v1, v2, v3);
            }
            if (which == 0) {
                float gg = 0.f;
#pragma unroll
                for (int w8 = 0; w8 < 8; w8++) gg += part[w8 * 256 + e];
                red4(&g_acc4[r * 4], cds[e] * gg, cds[256 + e] * gg,
                     cds[512 + e] * gg, 1.0f);
            }
        }
    }
}

// ======== node kernel (proven R2 version, acc4-adapted) ========
template <int RW>
__device__ __forceinline__ void gemm_t(const float* __restrict__ st,
                                       const float* __restrict__ w,
                                       const float* __restrict__ bias,
                                       ull (&acc)[4][4], int fc, int er, int K) {
#pragma unroll
    for (int j = 0; j < 4; j++) {
        ull bb = d2(bias[4 * fc + j]);
#pragma unroll
        for (int p = 0; p < 4; p++) acc[p][j] = bb;
    }
    const int eg0 = 2 * er, eg1 = 2 * er + 1;
#pragma unroll 2
    for (int k0 = 0; k0 < K; k0 += 4) {
        int ss = (k0 >> 2) & 7;
        int o0 = ((eg0 ^ ss) << 2), o1 = ((eg1 ^ ss) << 2);
#pragma unroll
        for (int kk = 0; kk < 4; kk++) {
            const float* rp = st + (k0 + kk) * RW;
            ulonglong2 aA = *(const ulonglong2*)(rp + o0);
            ulonglong2 aB = *(const ulonglong2*)(rp + o1);
            float4 wv = *(const float4*)(w + (k0 + kk) * 64 + 4 * fc);
            ull b0 = d2(wv.x), b1 = d2(wv.y), b2 = d2(wv.z), b3 = d2(wv.w);
            acc[0][0] = ffma2(aA.x, b0, acc[0][0]);
            acc[1][0] = ffma2(aA.y, b0, acc[1][0]);
            acc[2][0] = ffma2(aB.x, b0, acc[2][0]);
            acc[3][0] = ffma2(aB.y, b0, acc[3][0]);
            acc[0][1] = ffma2(aA.x, b1, acc[0][1]);
            acc[1][1] = ffma2(aA.y, b1, acc[1][1]);
            acc[2][1] = ffma2(aB.x, b1, acc[2][1]);
            acc[3][1] = ffma2(aB.y, b1, acc[3][1]);
            acc[0][2] = ffma2(aA.x, b2, acc[0][2]);
            acc[1][2] = ffma2(aA.y, b2, acc[1][2]);
            acc[2][2] = ffma2(aB.x, b2, acc[2][2]);
            acc[3][2] = ffma2(aB.y, b2, acc[3][2]);
            acc[0][3] = ffma2(aA.x, b3, acc[0][3]);
            acc[1][3] = ffma2(aA.y, b3, acc[1][3]);
            acc[2][3] = ffma2(aB.x, b3, acc[2][3]);
            acc[3][3] = ffma2(aB.y, b3, acc[3][3]);
        }
    }
}

template <int RW>
__device__ __forceinline__ void store_silu_t4(float* st, ull (&acc)[4][4], int fc, int er) {
    int ss = fc & 7;
    int o0 = (((2 * er) ^ ss) << 2), o1 = (((2 * er + 1) ^ ss) << 2);
#pragma unroll
    for (int j = 0; j < 4; j++) {
        int r = 4 * fc + j;
        float2 f0 = u2f(acc[0][j]), f1 = u2f(acc[1][j]);
        float2 f2 = u2f(acc[2][j]), f3 = u2f(acc[3][j]);
        float4 v0 = make_float4(silu_f(f0.x), silu_f(f0.y), silu_f(f1.x), silu_f(f1.y));
        float4 v1 = make_float4(silu_f(f2.x), silu_f(f2.y), silu_f(f3.x), silu_f(f3.y));
        *(float4*)(st + r * RW + o0) = v0;
        *(float4*)(st + r * RW + o1) = v1;
    }
}

__global__ void __launch_bounds__(128, 2)
    k_node(const float* __restrict__ nw1, const float* __restrict__ nb1,
           const float* __restrict__ nw2, const float* __restrict__ nb2,
           const float* __restrict__ vw1, const float* __restrict__ vb1,
           const float* __restrict__ vw2, const float* __restrict__ vb2) {
    extern __shared__ __align__(16) float sm[];
    float* wn1 = sm;
    float* wn2 = wn1 + 8192;
    float* wv1 = wn2 + 4096;
    float* us = wv1 + 4096;
    float* nb1s = us + 8192;
    float* nb2s = nb1s + 64;
    float* vb1s = nb2s + 64;
    float* vw2s = vb1s + 64;
    float* phis = vw2s + 64;

    const int tid = threadIdx.x;
    const int fc = tid & 15;
    const int er = tid >> 4;

    for (int i = tid; i < 2048; i += 128) ((float4*)wn1)[i] = ((const float4*)nw1)[i];
    for (int i = tid; i < 1024; i += 128) {
        ((float4*)wn2)[i] = ((const float4*)nw2)[i];
        ((float4*)wv1)[i] = ((const float4*)vw1)[i];
    }
    if (tid < 64) {
        nb1s[tid] = nb1[tid];
        nb2s[tid] = nb2[tid];
        vb1s[tid] = vb1[tid];
        vw2s[tid] = vw2[tid];
    }
    const float vb2v = vb2[0];

    const int e = tid & 63;
    const int half = tid >> 6;
    const int ntile = (NN + TNN - 1) / TNN;
    for (int t = blockIdx.x; t < ntile; t += gridDim.x) {
        __syncthreads();
        int n0 = t * TNN;
        int n = n0 + e;
#pragma unroll
        for (int q = 0; q < 8; q++) {
            int kq = half * 8 + q;
            float4 hv = make_float4(0, 0, 0, 0), av = make_float4(0, 0, 0, 0);
            if (n < NN) {
                hv = *(const float4*)&g_h[n * 64 + 4 * kq];
                av = *(const float4*)&g_agg[n * 64 + 4 * kq];
            }
            us[sidx(4 * kq + 0, e, 64)] = hv.x;
            us[sidx(4 * kq + 1, e, 64)] = hv.y;
            us[sidx(4 * kq + 2, e, 64)] = hv.z;
            us[sidx(4 * kq + 3, e, 64)] = hv.w;
            us[sidx(64 + 4 * kq + 0, e, 64)] = av.x;
            us[sidx(64 + 4 * kq + 1, e, 64)] = av.y;
            us[sidx(64 + 4 * kq + 2, e, 64)] = av.z;
            us[sidx(64 + 4 * kq + 3, e, 64)] = av.w;
        }
        __syncthreads();

        ull acc[4][4];
        gemm_t<64>(us, wv1, vb1s, acc, fc, er, 64);
        {
            float gv[8] = {0.f, 0.f, 0.f, 0.f, 0.f, 0.f, 0.f, 0.f};
#pragma unroll
            for (int p = 0; p < 4; p++)
#pragma unroll
                for (int j = 0; j < 4; j++) {
                    float2 f = u2f(acc[p][j]);
                    float c = vw2s[4 * fc + j];
                    gv[2 * p] = fmaf(silu_f(f.x), c, gv[2 * p]);
                    gv[2 * p + 1] = fmaf(silu_f(f.y), c, gv[2 * p + 1]);
                }
#pragma unroll
            for (int m = 1; m < 16; m <<= 1)
#pragma unroll
                for (int i = 0; i < 8; i++)
                    gv[i] += __shfl_xor_sync(0xffffffffu, gv[i], m);
            if (fc == 0)
#pragma unroll
                for (int i = 0; i < 8; i++) phis[8 * er + i] = gv[i] + vb2v;
        }

        gemm_t<64>(us, wn1, nb1s, acc, fc, er, 128);
        __syncthreads();
        store_silu_t4<64>(us + 64 * 64, acc, fc, er);
        __syncthreads();

        gemm_t<64>(us + 64 * 64, wn2, nb2s, acc, fc, er, 64);
#pragma unroll
        for (int p = 0; p < 4; p++) {
            int nlo = n0 + 8 * er + 2 * p, nhi = nlo + 1;
#pragma unroll
            for (int j = 0; j < 4; j++) {
                float2 f = u2f(acc[p][j]);
                if (nlo < NN) g_h[nlo * 64 + 4 * fc + j] += f.x;
                if (nhi < NN) g_h[nhi * 64 + 4 * fc + j] += f.y;
            }
        }

        if (tid < TNN) {
            int nu = n0 + tid;
            if (nu < NN) {
                float cnt = g_acc4[nu * 4 + 3];
                float inv = 1.0f / fmaxf(cnt, 1.0f);
                float phi = phis[tid];
#pragma unroll
                for (int d = 0; d < 3; d++) {
                    float a = g_acc4[nu * 4 + d] * inv;
                    float vn = g_v[nu * 3 + d] + a + phi * g_iv[nu * 3 + d];
                    g_v[nu * 3 + d] = vn;
                    g_x[nu * 3 + d] += vn;
                }
                *(float4*)&g_acc4[nu * 4] = make_float4(0.f, 0.f, 0.f, 0.f);
            }
        }
        for (int i = tid; i < TNN * 64; i += 128) {
            int nz = n0 + (i >> 6);
            if (nz < NN) g_agg[nz * 64 + (i & 63)] = 0.f;
        }
    }
}

// ---------------- output: [x | h | v] ----------------
__global__ void k_copyout(float* __restrict__ out) {
    int i = blockIdx.x * blockDim.x + threadIdx.x;
    if (i < NN * 3) out[i] = g_x[i];
    if (i < NN * HD) out[NN * 3 + i] = g_h[i];
    if (i < NN * 3) out[NN * 3 + NN * HD + i] = g_v[i];
}

extern "C" void kernel_launch(void* const* d_in, const int* in_sizes, int n_in,
                              void* d_out, int out_size) {
    const float* his = (const float*)d_in[0];
    const float* loc = (const float*)d_in[1];
    const void* edges = d_in[2];
    const float* vel = (const float*)d_in[3];
    const float* eattr = (const float*)d_in[4];
    const float* emb_w = (const float*)d_in[5];
    const float* emb_b = (const float*)d_in[6];
    const float* ew1 = (const float*)d_in[7];
    const float* eb1 = (const float*)d_in[8];
    const float* ew2 = (const float*)d_in[9];
    const float* eb2 = (const float*)d_in[10];
    const float* nw1 = (const float*)d_in[11];
    const float* nb1 = (const float*)d_in[12];
    const float* nw2 = (const float*)d_in[13];
    const float* nb2 = (const float*)d_in[14];
    const float* cw1 = (const float*)d_in[15];
    const float* cb1 = (const float*)d_in[16];
    const float* cw2 = (const float*)d_in[17];
    const float* vw1 = (const float*)d_in[18];
    const float* vb1 = (const float*)d_in[19];
    const float* vw2 = (const float*)d_in[20];
    const float* vb2 = (const float*)d_in[21];

    // edge smem: w 16576 + ins 33536 + part 2048 + biases 256 + cds 768
    //          = 53184 floats + 512 ints = 214784 B
    size_t esm = (size_t)53184 * 4 + 512 * sizeof(int);
    size_t nsm = (size_t)(8192 + 4096 + 4096 + 8192 + 4 * 64 + 64) * 4;
    cudaFuncSetAttribute(k_edge, cudaFuncAttributeMaxDynamicSharedMemorySize, (int)esm);
    cudaFuncSetAttribute(k_node, cudaFuncAttributeMaxDynamicSharedMemorySize, (int)nsm);

    k_detect<<<1, 1>>>(edges);
    k_init<<<(NN * HD + 255) / 256, 256>>>(his, loc, vel, emb_w, emb_b);
    for (int l = 0; l < NLAYERS; l++) {
        k_edge<<<148, 512, esm>>>(edges, eattr, ew1, eb1, ew2, eb2, cw1, cb1, cw2);
        k_node<<<157, 128, nsm>>>(nw1, nb1, nw2, nb2, vw1, vb1, vw2, vb2);
    }
    k_copyout<<<(NN * HD + 255) / 256, 256>>>((float*)d_out);
}

// round 8
// speedup vs baseline: 2.5684x; 1.5634x over previous
#include <cuda_runtime.h>

#define NN 10000
#define NE 320000
#define HD 64
#define NLAYERS 4
#define TE 256   // edges per tile (edge kernel)
#define TNN 64   // nodes per tile (node/proj kernels)

typedef unsigned long long ull;

// ---------------- scratch state (allocation-free) ----------------
__device__ __align__(16) float g_h[NN * HD];
__device__ __align__(16) float g_agg[NN * HD];
__device__ __align__(16) float g_pa[NN * HD];    // h @ W1[0:64]
__device__ __align__(16) float g_pb[NN * HD];    // h @ W1[64:128]
__device__ __align__(16) float g_acc4[NN * 4];   // [dx,dy,dz,cnt] per node
__device__ float g_x[NN * 3];
__device__ float g_v[NN * 3];
__device__ float g_iv[NN * 3];
__device__ float g_zero64[64];                   // zero-initialized
__device__ int g_edge64;

__device__ __forceinline__ float silu_f(float x) {
    return __fdividef(x, 1.0f + __expf(-x));
}

// packed f32x2 helpers
__device__ __forceinline__ ull d2(float x) {
    ull r;
    unsigned u = __float_as_uint(x);
    asm("mov.b64 %0, {%1, %1};" : "=l"(r) : "r"(u));
    return r;
}
__device__ __forceinline__ ull ffma2(ull a, ull b, ull c) {
    ull d;
    asm("fma.rn.f32x2 %0, %1, %2, %3;" : "=l"(d) : "l"(a), "l"(b), "l"(c));
    return d;
}
__device__ __forceinline__ float2 u2f(ull v) {
    unsigned lo, hi;
    asm("mov.b64 {%0, %1}, %2;" : "=r"(lo), "=r"(hi) : "l"(v));
    return make_float2(__uint_as_float(lo), __uint_as_float(hi));
}

// 16B vector reduction (sm_90+)
__device__ __forceinline__ void red4(float* p, float a, float b, float c, float d) {
    asm volatile("red.global.add.v4.f32 [%0], {%1, %2, %3, %4};"
                 :: "l"(p), "f"(a), "f"(b), "f"(c), "f"(d) : "memory");
}

// swizzled staging index (16B-granule xor)
__device__ __forceinline__ int sidx(int k, int e, int RW) {
    return k * RW + ((((e >> 2) ^ ((k >> 2) & 7)) << 2) | (e & 3));
}

__device__ __forceinline__ int edge_idx(const void* edges, long long i) {
    if (g_edge64) return (int)((const long long*)edges)[i];
    return ((const int*)edges)[i];
}

__global__ void k_detect(const void* edges) {
    const int* p = (const int*)edges;
    int is64 = 1;
    for (int i = 1; i < 64; i += 2)
        if (p[i] != 0) is64 = 0;
    g_edge64 = is64;
}

__global__ void k_init(const float* __restrict__ his, const float* __restrict__ loc,
                       const float* __restrict__ vel, const float* __restrict__ emb_w,
                       const float* __restrict__ emb_b) {
    int idx = blockIdx.x * blockDim.x + threadIdx.x;
    if (idx < NN * HD) {
        int n = idx >> 6, j = idx & 63;
        float a = emb_b[j];
#pragma unroll
        for (int i = 0; i < 4; i++) a = fmaf(his[n * 4 + i], emb_w[i * 64 + j], a);
        g_h[idx] = a;
        g_agg[idx] = 0.f;
    }
    if (idx < NN * 4) g_acc4[idx] = 0.f;
    if (idx < NN * 3) {
        g_x[idx] = loc[idx];
        g_v[idx] = vel[idx];
    }
    if (idx < NN) {
        float vx = vel[idx * 3], vy = vel[idx * 3 + 1], vz = vel[idx * 3 + 2];
        float inv = 1.0f / (sqrtf(vx * vx + vy * vy + vz * vz) + 1e-8f);
        g_iv[idx * 3] = vx * inv;
        g_iv[idx * 3 + 1] = vy * inv;
        g_iv[idx * 3 + 2] = vz * inv;
    }
}

// ---- edge GEMM (R6-proven): warp owns feature octet, lane owns 4 edges ----
__device__ __forceinline__ void gemm_w(const float* __restrict__ st,
                                       const float* __restrict__ w,
                                       const float* __restrict__ bias,
                                       ull (&acc)[8][2], int wf, int lp, int K) {
#pragma unroll
    for (int j = 0; j < 8; j++) {
        ull bb = d2(bias[8 * wf + j]);
        acc[j][0] = bb;
        acc[j][1] = bb;
    }
    const float* wp = w + 8 * wf;
    for (int k0 = 0; k0 < K; k0 += 4) {
        int s = (k0 >> 2) & 7;
        int o = ((lp ^ s) << 2);
#pragma unroll
        for (int kk = 0; kk < 4; kk++) {
            ulonglong2 a = *(const ulonglong2*)(st + (k0 + kk) * 256 + o);
            const float* wr = wp + (k0 + kk) * 64;
            float4 w0 = *(const float4*)(wr);      // warp-uniform -> broadcast
            float4 w1 = *(const float4*)(wr + 4);
            ull b0 = d2(w0.x), b1 = d2(w0.y), b2 = d2(w0.z), b3 = d2(w0.w);
            ull b4 = d2(w1.x), b5 = d2(w1.y), b6 = d2(w1.z), b7 = d2(w1.w);
            acc[0][0] = ffma2(a.x, b0, acc[0][0]);
            acc[0][1] = ffma2(a.y, b0, acc[0][1]);
            acc[1][0] = ffma2(a.x, b1, acc[1][0]);
            acc[1][1] = ffma2(a.y, b1, acc[1][1]);
            acc[2][0] = ffma2(a.x, b2, acc[2][0]);
            acc[2][1] = ffma2(a.y, b2, acc[2][1]);
            acc[3][0] = ffma2(a.x, b3, acc[3][0]);
            acc[3][1] = ffma2(a.y, b3, acc[3][1]);
            acc[4][0] = ffma2(a.x, b4, acc[4][0]);
            acc[4][1] = ffma2(a.y, b4, acc[4][1]);
            acc[5][0] = ffma2(a.x, b5, acc[5][0]);
            acc[5][1] = ffma2(a.y, b5, acc[5][1]);
            acc[6][0] = ffma2(a.x, b6, acc[6][0]);
            acc[6][1] = ffma2(a.y, b6, acc[6][1]);
            acc[7][0] = ffma2(a.x, b7, acc[7][0]);
            acc[7][1] = ffma2(a.y, b7, acc[7][1]);
        }
    }
}

// silu + feature-major swizzled store of the warp's 8x4 tile
__device__ __forceinline__ void store_w(float* st, ull (&acc)[8][2], int wf, int lp) {
#pragma unroll
    for (int j = 0; j < 8; j++) {
        int r = 8 * wf + j;
        int s = (r >> 2) & 7;
        float2 f0 = u2f(acc[j][0]), f1 = u2f(acc[j][1]);
        *(float4*)(st + r * 256 + ((lp ^ s) << 2)) =
            make_float4(silu_f(f0.x), silu_f(f0.y), silu_f(f1.x), silu_f(f1.y));
    }
}

// ---------------- edge kernel: 256-edge tiles, 512 threads, NO GEMM1 ----------------
__global__ void __launch_bounds__(512, 1)
    k_edge(const void* __restrict__ edges, const float* __restrict__ edge_attr,
           const float* __restrict__ ew1, const float* __restrict__ eb1,
           const float* __restrict__ ew2, const float* __restrict__ eb2,
           const float* __restrict__ cw1, const float* __restrict__ cb1,
           const float* __restrict__ cw2) {
    extern __shared__ __align__(16) float sm[];
    float* w2s = sm;                    // 4096
    float* w3s = w2s + 4096;            // 4096
    float* ins = w3s + 4096;            // 64*256 = 16384
    float* part = ins + 16384;          // 8*256 gate partials
    float* wtl = part + 2048;           // 64*4: {wr, wa0, wa1, b1} per k
    float* b2s = wtl + 256;             // 64
    float* b3s = b2s + 64;
    float* c2s = b3s + 64;
    int* rs = (int*)(c2s + 64);         // 256
    int* cs = rs + 256;                 // 256

    const int tid = threadIdx.x;
    const int lane = tid & 31;
    const int warp = tid >> 5;
    const int wf = warp & 7;              // feature octet
    const int we = warp >> 3;             // edge half (0/1)
    const int lp = we * 32 + lane;        // edge granule 0..63
    const int e = tid & 255;
    const int which = tid >> 8;           // k-half 0/1 for stage & scatter

    for (int i = tid; i < 1024; i += 512) {
        ((float4*)w2s)[i] = ((const float4*)ew2)[i];
        ((float4*)w3s)[i] = ((const float4*)cw1)[i];
    }
    if (tid < 64) {
        wtl[tid * 4 + 0] = ew1[128 * 64 + tid];   // radial row
        wtl[tid * 4 + 1] = ew1[129 * 64 + tid];   // eattr row 0
        wtl[tid * 4 + 2] = ew1[130 * 64 + tid];   // eattr row 1
        wtl[tid * 4 + 3] = eb1[tid];
        b2s[tid] = eb2[tid];
        b3s[tid] = cb1[tid];
        c2s[tid] = cw2[tid];
    }

    const int ntile = NE / TE;
    for (int t = blockIdx.x; t < ntile; t += gridDim.x) {
        __syncthreads();
        long long e0 = (long long)t * TE;
        if (which == 0) {
            rs[e] = edge_idx(edges, e0 + e);
            cs[e] = edge_idx(edges, (long long)NE + e0 + e);
        }
        __syncthreads();

        // stage t1 = silu(Pa[row] + Pb[col] + rad*wr + ea@we + b1); 2 threads/edge split k
        int r = rs[e], c = cs[e];
        float dx = g_x[r * 3] - g_x[c * 3];
        float dy = g_x[r * 3 + 1] - g_x[c * 3 + 1];
        float dz = g_x[r * 3 + 2] - g_x[c * 3 + 2];
        float rad = dx * dx + dy * dy + dz * dz;
        float2 ea = *(const float2*)&edge_attr[(e0 + e) * 2];
        {
            const float4* pa = (const float4*)&g_pa[r * 64 + which * 32];
            const float4* pb = (const float4*)&g_pb[c * 64 + which * 32];
#pragma unroll
            for (int q = 0; q < 8; q++) {
                int k = which * 32 + 4 * q;
                float4 va = pa[q], vb = pb[q];
                float4 t0 = *(const float4*)&wtl[(k + 0) * 4];
                float4 t1 = *(const float4*)&wtl[(k + 1) * 4];
                float4 t2 = *(const float4*)&wtl[(k + 2) * 4];
                float4 t3 = *(const float4*)&wtl[(k + 3) * 4];
                float v0 = va.x + vb.x + rad * t0.x + ea.x * t0.y + ea.y * t0.z + t0.w;
                float v1 = va.y + vb.y + rad * t1.x + ea.x * t1.y + ea.y * t1.z + t1.w;
                float v2 = va.z + vb.z + rad * t2.x + ea.x * t2.y + ea.y * t2.z + t2.w;
                float v3 = va.w + vb.w + rad * t3.x + ea.x * t3.y + ea.y * t3.z + t3.w;
                ins[sidx(k + 0, e, 256)] = silu_f(v0);
                ins[sidx(k + 1, e, 256)] = silu_f(v1);
                ins[sidx(k + 2, e, 256)] = silu_f(v2);
                ins[sidx(k + 3, e, 256)] = silu_f(v3);
            }
        }
        __syncthreads();

        ull acc[8][2];
        // GEMM2: t1@[64,64] + b2, silu -> ef (in-place)
        gemm_w(ins, w2s, b2s, acc, wf, lp, 64);
        __syncthreads();
        store_w(ins, acc, wf, lp);
        __syncthreads();

        // GEMM3: ef@cw1 + b3, silu, dot cw2 -> per-warp gate partials
        gemm_w(ins, w3s, b3s, acc, wf, lp, 64);
        {
            float g0 = 0.f, g1 = 0.f, g2 = 0.f, g3 = 0.f;
#pragma unroll
            for (int j = 0; j < 8; j++) {
                float cj = c2s[8 * wf + j];
                float2 f0 = u2f(acc[j][0]), f1 = u2f(acc[j][1]);
                g0 = fmaf(silu_f(f0.x), cj, g0);
                g1 = fmaf(silu_f(f0.y), cj, g1);
                g2 = fmaf(silu_f(f1.x), cj, g2);
                g3 = fmaf(silu_f(f1.y), cj, g3);
            }
            *(float4*)(part + wf * 256 + 4 * lp) = make_float4(g0, g1, g2, g3);
        }
        __syncthreads();

        // scatter: agg += ef (vector red), acc4 += [cd*gate, 1]
        {
#pragma unroll
            for (int q = 0; q < 8; q++) {
                int f0 = which * 32 + 4 * q;
                float v0 = ins[sidx(f0 + 0, e, 256)];
                float v1 = ins[sidx(f0 + 1, e, 256)];
                float v2 = ins[sidx(f0 + 2, e, 256)];
                float v3 = ins[sidx(f0 + 3, e, 256)];
                red4(&g_agg[r * 64 + f0], v0, v1, v2, v3);
            }
            if (which == 0) {
                float gg = 0.f;
#pragma unroll
                for (int w8 = 0; w8 < 8; w8++) gg += part[w8 * 256 + e];
                red4(&g_acc4[r * 4], dx * gg, dy * gg, dz * gg, 1.0f);
            }
        }
    }
}

// ======== node-style GEMM micro-kernel (proven) ========
template <int RW>
__device__ __forceinline__ void gemm_t(const float* __restrict__ st,
                                       const float* __restrict__ w,
                                       const float* __restrict__ bias,
                                       ull (&acc)[4][4], int fc, int er, int K) {
#pragma unroll
    for (int j = 0; j < 4; j++) {
        ull bb = d2(bias[4 * fc + j]);
#pragma unroll
        for (int p = 0; p < 4; p++) acc[p][j] = bb;
    }
    const int eg0 = 2 * er, eg1 = 2 * er + 1;
#pragma unroll 2
    for (int k0 = 0; k0 < K; k0 += 4) {
        int ss = (k0 >> 2) & 7;
        int o0 = ((eg0 ^ ss) << 2), o1 = ((eg1 ^ ss) << 2);
#pragma unroll
        for (int kk = 0; kk < 4; kk++) {
            const float* rp = st + (k0 + kk) * RW;
            ulonglong2 aA = *(const ulonglong2*)(rp + o0);
            ulonglong2 aB = *(const ulonglong2*)(rp + o1);
            float4 wv = *(const float4*)(w + (k0 + kk) * 64 + 4 * fc);
            ull b0 = d2(wv.x), b1 = d2(wv.y), b2 = d2(wv.z), b3 = d2(wv.w);
            acc[0][0] = ffma2(aA.x, b0, acc[0][0]);
            acc[1][0] = ffma2(aA.y, b0, acc[1][0]);
            acc[2][0] = ffma2(aB.x, b0, acc[2][0]);
            acc[3][0] = ffma2(aB.y, b0, acc[3][0]);
            acc[0][1] = ffma2(aA.x, b1, acc[0][1]);
            acc[1][1] = ffma2(aA.y, b1, acc[1][1]);
            acc[2][1] = ffma2(aB.x, b1, acc[2][1]);
            acc[3][1] = ffma2(aB.y, b1, acc[3][1]);
            acc[0][2] = ffma2(aA.x, b2, acc[0][2]);
            acc[1][2] = ffma2(aA.y, b2, acc[1][2]);
            acc[2][2] = ffma2(aB.x, b2, acc[2][2]);
            acc[3][2] = ffma2(aB.y, b2, acc[3][2]);
            acc[0][3] = ffma2(aA.x, b3, acc[0][3]);
            acc[1][3] = ffma2(aA.y, b3, acc[1][3]);
            acc[2][3] = ffma2(aB.x, b3, acc[2][3]);
            acc[3][3] = ffma2(aB.y, b3, acc[3][3]);
        }
    }
}

template <int RW>
__device__ __forceinline__ void store_silu_t4(float* st, ull (&acc)[4][4], int fc, int er) {
    int ss = fc & 7;
    int o0 = (((2 * er) ^ ss) << 2), o1 = (((2 * er + 1) ^ ss) << 2);
#pragma unroll
    for (int j = 0; j < 4; j++) {
        int r = 4 * fc + j;
        float2 f0 = u2f(acc[0][j]), f1 = u2f(acc[1][j]);
        float2 f2 = u2f(acc[2][j]), f3 = u2f(acc[3][j]);
        float4 v0 = make_float4(silu_f(f0.x), silu_f(f0.y), silu_f(f1.x), silu_f(f1.y));
        float4 v1 = make_float4(silu_f(f2.x), silu_f(f2.y), silu_f(f3.x), silu_f(f3.y));
        *(float4*)(st + r * RW + o0) = v0;
        *(float4*)(st + r * RW + o1) = v1;
    }
}

// ---------------- proj kernel: Pa = h@W1[0:64], Pb = h@W1[64:128] ----------------
__global__ void __launch_bounds__(128, 2)
    k_proj(const float* __restrict__ ew1) {
    extern __shared__ __align__(16) float sm[];
    float* wa = sm;             // 4096
    float* wb = wa + 4096;      // 4096
    float* us = wb + 4096;      // 64*64

    const int tid = threadIdx.x;
    const int fc = tid & 15;
    const int er = tid >> 4;
    const int e = tid & 63;
    const int half = tid >> 6;

    for (int i = tid; i < 1024; i += 128) {
        ((float4*)wa)[i] = ((const float4*)ew1)[i];
        ((float4*)wb)[i] = ((const float4*)(ew1 + 4096))[i];
    }

    const int ntile = (NN + TNN - 1) / TNN;
    for (int t = blockIdx.x; t < ntile; t += gridDim.x) {
        __syncthreads();
        int n0 = t * TNN;
        int n = n0 + e;
#pragma unroll
        for (int q = 0; q < 8; q++) {
            int kq = half * 8 + q;
            float4 hv = make_float4(0, 0, 0, 0);
            if (n < NN) hv = *(const float4*)&g_h[n * 64 + 4 * kq];
            us[sidx(4 * kq + 0, e, 64)] = hv.x;
            us[sidx(4 * kq + 1, e, 64)] = hv.y;
            us[sidx(4 * kq + 2, e, 64)] = hv.z;
            us[sidx(4 * kq + 3, e, 64)] = hv.w;
        }
        __syncthreads();

        ull acc[4][4];
        gemm_t<64>(us, wa, g_zero64, acc, fc, er, 64);
#pragma unroll
        for (int p = 0; p < 4; p++) {
            int nlo = n0 + 8 * er + 2 * p, nhi = nlo + 1;
#pragma unroll
            for (int j = 0; j < 4; j++) {
                float2 f = u2f(acc[p][j]);
                if (nlo < NN) g_pa[nlo * 64 + 4 * fc + j] = f.x;
                if (nhi < NN) g_pa[nhi * 64 + 4 * fc + j] = f.y;
            }
        }
        gemm_t<64>(us, wb, g_zero64, acc, fc, er, 64);
#pragma unroll
        for (int p = 0; p < 4; p++) {
            int nlo = n0 + 8 * er + 2 * p, nhi = nlo + 1;
#pragma unroll
            for (int j = 0; j < 4; j++) {
                float2 f = u2f(acc[p][j]);
                if (nlo < NN) g_pb[nlo * 64 + 4 * fc + j] = f.x;
                if (nhi < NN) g_pb[nhi * 64 + 4 * fc + j] = f.y;
            }
        }
    }
}

// ---------------- node kernel (R6 version) ----------------
__global__ void __launch_bounds__(128, 2)
    k_node(const float* __restrict__ nw1, const float* __restrict__ nb1,
           const float* __restrict__ nw2, const float* __restrict__ nb2,
           const float* __restrict__ vw1, const float* __restrict__ vb1,
           const float* __restrict__ vw2, const float* __restrict__ vb2) {
    extern __shared__ __align__(16) float sm[];
    float* wn1 = sm;
    float* wn2 = wn1 + 8192;
    float* wv1 = wn2 + 4096;
    float* us = wv1 + 4096;
    float* nb1s = us + 8192;
    float* nb2s = nb1s + 64;
    float* vb1s = nb2s + 64;
    float* vw2s = vb1s + 64;
    float* phis = vw2s + 64;

    const int tid = threadIdx.x;
    const int fc = tid & 15;
    const int er = tid >> 4;

    for (int i = tid; i < 2048; i += 128) ((float4*)wn1)[i] = ((const float4*)nw1)[i];
    for (int i = tid; i < 1024; i += 128) {
        ((float4*)wn2)[i] = ((const float4*)nw2)[i];
        ((float4*)wv1)[i] = ((const float4*)vw1)[i];
    }
    if (tid < 64) {
        nb1s[tid] = nb1[tid];
        nb2s[tid] = nb2[tid];
        vb1s[tid] = vb1[tid];
        vw2s[tid] = vw2[tid];
    }
    const float vb2v = vb2[0];

    const int e = tid & 63;
    const int half = tid >> 6;
    const int ntile = (NN + TNN - 1) / TNN;
    for (int t = blockIdx.x; t < ntile; t += gridDim.x) {
        __syncthreads();
        int n0 = t * TNN;
        int n = n0 + e;
#pragma unroll
        for (int q = 0; q < 8; q++) {
            int kq = half * 8 + q;
            float4 hv = make_float4(0, 0, 0, 0), av = make_float4(0, 0, 0, 0);
            if (n < NN) {
                hv = *(const float4*)&g_h[n * 64 + 4 * kq];
                av = *(const float4*)&g_agg[n * 64 + 4 * kq];
            }
            us[sidx(4 * kq + 0, e, 64)] = hv.x;
            us[sidx(4 * kq + 1, e, 64)] = hv.y;
            us[sidx(4 * kq + 2, e, 64)] = hv.z;
            us[sidx(4 * kq + 3, e, 64)] = hv.w;
            us[sidx(64 + 4 * kq + 0, e, 64)] = av.x;
            us[sidx(64 + 4 * kq + 1, e, 64)] = av.y;
            us[sidx(64 + 4 * kq + 2, e, 64)] = av.z;
            us[sidx(64 + 4 * kq + 3, e, 64)] = av.w;
        }
        __syncthreads();

        ull acc[4][4];
        gemm_t<64>(us, wv1, vb1s, acc, fc, er, 64);
        {
            float gv[8] = {0.f, 0.f, 0.f, 0.f, 0.f, 0.f, 0.f, 0.f};
#pragma unroll
            for (int p = 0; p < 4; p++)
#pragma unroll
                for (int j = 0; j < 4; j++) {
                    float2 f = u2f(acc[p][j]);
                    float cj = vw2s[4 * fc + j];
                    gv[2 * p] = fmaf(silu_f(f.x), cj, gv[2 * p]);
                    gv[2 * p + 1] = fmaf(silu_f(f.y), cj, gv[2 * p + 1]);
                }
#pragma unroll
            for (int m = 1; m < 16; m <<= 1)
#pragma unroll
                for (int i = 0; i < 8; i++)
                    gv[i] += __shfl_xor_sync(0xffffffffu, gv[i], m);
            if (fc == 0)
#pragma unroll
                for (int i = 0; i < 8; i++) phis[8 * er + i] = gv[i] + vb2v;
        }

        gemm_t<64>(us, wn1, nb1s, acc, fc, er, 128);
        __syncthreads();
        store_silu_t4<64>(us + 64 * 64, acc, fc, er);
        __syncthreads();

        gemm_t<64>(us + 64 * 64, wn2, nb2s, acc, fc, er, 64);
#pragma unroll
        for (int p = 0; p < 4; p++) {
            int nlo = n0 + 8 * er + 2 * p, nhi = nlo + 1;
#pragma unroll
            for (int j = 0; j < 4; j++) {
                float2 f = u2f(acc[p][j]);
                if (nlo < NN) g_h[nlo * 64 + 4 * fc + j] += f.x;
                if (nhi < NN) g_h[nhi * 64 + 4 * fc + j] += f.y;
            }
        }

        if (tid < TNN) {
            int nu = n0 + tid;
            if (nu < NN) {
                float cnt = g_acc4[nu * 4 + 3];
                float inv = 1.0f / fmaxf(cnt, 1.0f);
                float phi = phis[tid];
#pragma unroll
                for (int d = 0; d < 3; d++) {
                    float a = g_acc4[nu * 4 + d] * inv;
                    float vn = g_v[nu * 3 + d] + a + phi * g_iv[nu * 3 + d];
                    g_v[nu * 3 + d] = vn;
                    g_x[nu * 3 + d] += vn;
                }
                *(float4*)&g_acc4[nu * 4] = make_float4(0.f, 0.f, 0.f, 0.f);
            }
        }
        for (int i = tid; i < TNN * 64; i += 128) {
            int nz = n0 + (i >> 6);
            if (nz < NN) g_agg[nz * 64 + (i & 63)] = 0.f;
        }
    }
}

// ---------------- output: [x | h | v] ----------------
__global__ void k_copyout(float* __restrict__ out) {
    int i = blockIdx.x * blockDim.x + threadIdx.x;
    if (i < NN * 3) out[i] = g_x[i];
    if (i < NN * HD) out[NN * 3 + i] = g_h[i];
    if (i < NN * 3) out[NN * 3 + NN * HD + i] = g_v[i];
}

extern "C" void kernel_launch(void* const* d_in, const int* in_sizes, int n_in,
                              void* d_out, int out_size) {
    const float* his = (const float*)d_in[0];
    const float* loc = (const float*)d_in[1];
    const void* edges = d_in[2];
    const float* vel = (const float*)d_in[3];
    const float* eattr = (const float*)d_in[4];
    const float* emb_w = (const float*)d_in[5];
    const float* emb_b = (const float*)d_in[6];
    const float* ew1 = (const float*)d_in[7];
    const float* eb1 = (const float*)d_in[8];
    const float* ew2 = (const float*)d_in[9];
    const float* eb2 = (const float*)d_in[10];
    const float* nw1 = (const float*)d_in[11];
    const float* nb1 = (const float*)d_in[12];
    const float* nw2 = (const float*)d_in[13];
    const float* nb2 = (const float*)d_in[14];
    const float* cw1 = (const float*)d_in[15];
    const float* cb1 = (const float*)d_in[16];
    const float* cw2 = (const float*)d_in[17];
    const float* vw1 = (const float*)d_in[18];
    const float* vb1 = (const float*)d_in[19];
    const float* vw2 = (const float*)d_in[20];
    const float* vb2 = (const float*)d_in[21];

    // edge smem: w2 4096 + w3 4096 + ins 16384 + part 2048 + wtl 256 + b 192
    //          = 27072 floats + 512 ints = 110336 B
    size_t esm = (size_t)27072 * 4 + 512 * sizeof(int);
    size_t nsm = (size_t)(8192 + 4096 + 4096 + 8192 + 4 * 64 + 64) * 4;
    size_t psm = (size_t)(4096 + 4096 + 4096) * 4;
    cudaFuncSetAttribute(k_edge, cudaFuncAttributeMaxDynamicSharedMemorySize, (int)esm);
    cudaFuncSetAttribute(k_node, cudaFuncAttributeMaxDynamicSharedMemorySize, (int)nsm);
    cudaFuncSetAttribute(k_proj, cudaFuncAttributeMaxDynamicSharedMemorySize, (int)psm);

    k_detect<<<1, 1>>>(edges);
    k_init<<<(NN * HD + 255) / 256, 256>>>(his, loc, vel, emb_w, emb_b);
    k_proj<<<157, 128, psm>>>(ew1);
    for (int l = 0; l < NLAYERS; l++) {
        k_edge<<<148, 512, esm>>>(edges, eattr, ew1, eb1, ew2, eb2, cw1, cb1, cw2);
        k_node<<<157, 128, nsm>>>(nw1, nb1, nw2, nb2, vw1, vb1, vw2, vb2);
        if (l < NLAYERS - 1) k_proj<<<157, 128, psm>>>(ew1);
    }
    k_copyout<<<(NN * HD + 255) / 256, 256>>>((float*)d_out);
}